// round 9
// baseline (speedup 1.0000x reference)
#include <cuda_runtime.h>
#include <cuda_fp16.h>
#include <cstdint>
#include <cstddef>

// B=1024, F=512, N=8 — HMMA fp16 (fp32 accum), split-precision where needed.
// G1: 2-term ([hi|lo] x hi-dup). G2/G3: 3-term. conv: 1-term fp16 with the A
// operand read DIRECTLY from fp16 vaT (G2 epilogue output) using di-shifted
// row indexing in the cp.async stage — no materialized im2col operand.

#define LDK 40   // smem row stride in halves (80B, conflict-free ldmatrix)

// ---------------- static scratch ----------------
__device__ unsigned short g_xcat3[(size_t)1024 * 2048];   // A-split of [vx|ax]
__device__ unsigned short g_W13[(size_t)4096 * 2048];     // B-split of W1
__device__ unsigned short g_h3[(size_t)8 * 1024 * 1024];  // [z][b][hi512|lo512]
__device__ unsigned short g_W23[(size_t)4096 * 1024];     // B-split of W2
__device__ unsigned short g_vaT16[(size_t)1024 * 8 * 512];// fp16 va, [b][i][f]
__device__ unsigned short g_W3[(size_t)1536 * 1536];      // conv B, fp16 hi only
__device__ float g_Y[(size_t)8192 * 1536];                // conv out
__device__ unsigned short g_p3[(size_t)1024 * 4096];      // pooled split
__device__ unsigned short g_A23[(size_t)512 * 4096];      // conv2-collapsed split
__device__ __align__(16) unsigned short g_zero[64];       // zero page (bss-zeroed)

// ---------------- helpers ----------------
union Pack8 { unsigned short s[8]; uint4 v; };
__device__ __forceinline__ void split_hi_lo(float x, unsigned short& hi, unsigned short& lo) {
    __half h = __float2half_rn(x);
    float hf = __half2float(h);
    __half l = __float2half_rn(x - hf);
    hi = __half_as_ushort(h);
    lo = __half_as_ushort(l);
}
__device__ __forceinline__ uint32_t smem_u32(const void* p) {
    uint32_t a;
    asm("{ .reg .u64 t; cvta.to.shared.u64 t, %1; cvt.u32.u64 %0, t; }" : "=r"(a) : "l"(p));
    return a;
}
__device__ __forceinline__ void ldmatrix_x4(uint32_t& r0, uint32_t& r1, uint32_t& r2, uint32_t& r3,
                                            uint32_t addr) {
    asm volatile("ldmatrix.sync.aligned.m8n8.x4.shared.b16 {%0,%1,%2,%3}, [%4];"
                 : "=r"(r0), "=r"(r1), "=r"(r2), "=r"(r3) : "r"(addr));
}
__device__ __forceinline__ void mma_16816(float* c, const uint32_t* a, const uint32_t* b) {
    asm volatile("mma.sync.aligned.m16n8k16.row.col.f32.f16.f16.f32 "
                 "{%0,%1,%2,%3}, {%4,%5,%6,%7}, {%8,%9}, {%0,%1,%2,%3};"
                 : "+f"(c[0]), "+f"(c[1]), "+f"(c[2]), "+f"(c[3])
                 : "r"(a[0]), "r"(a[1]), "r"(a[2]), "r"(a[3]), "r"(b[0]), "r"(b[1]));
}
__device__ __forceinline__ void cp_async16(uint32_t dst, const void* src) {
    asm volatile("cp.async.cg.shared.global [%0], [%1], 16;" :: "r"(dst), "l"(src));
}
#define CP_COMMIT() asm volatile("cp.async.commit_group;" ::: "memory")
#define CP_WAIT0()  asm volatile("cp.async.wait_group 0;" ::: "memory")

// ---------------- operand builders ----------------
__global__ void concat_split_kernel(const float* __restrict__ vx, const float* __restrict__ ax) {
    int idx = blockIdx.x * blockDim.x + threadIdx.x;  // 1024*128
    int kv = idx & 127, b = idx >> 7;
    const float* src = (kv < 64) ? (vx + (size_t)b * 512 + kv * 8)
                                 : (ax + (size_t)b * 512 + (kv - 64) * 8);
    float4 x0 = *(const float4*)src, x1 = *(const float4*)(src + 4);
    float vals[8] = {x0.x, x0.y, x0.z, x0.w, x1.x, x1.y, x1.z, x1.w};
    Pack8 hi, lo;
    #pragma unroll
    for (int j = 0; j < 8; j++) split_hi_lo(vals[j], hi.s[j], lo.s[j]);
    size_t e0 = (size_t)b * 2048 + kv * 8;
    *(uint4*)(g_xcat3 + e0)        = hi.v;
    *(uint4*)(g_xcat3 + e0 + 1024) = lo.v;
}

__global__ void split3B_kernel(const float* __restrict__ src, unsigned short* __restrict__ dst,
                               int Kv /* K/8 */, int K) {
    int idx = blockIdx.x * blockDim.x + threadIdx.x;  // R*Kv
    int kv = idx % Kv, r = idx / Kv;
    const float* s = src + (size_t)r * K + kv * 8;
    float4 x0 = *(const float4*)s, x1 = *(const float4*)(s + 4);
    float vals[8] = {x0.x, x0.y, x0.z, x0.w, x1.x, x1.y, x1.z, x1.w};
    Pack8 hi, lo;
    #pragma unroll
    for (int j = 0; j < 8; j++) split_hi_lo(vals[j], hi.s[j], lo.s[j]);
    size_t e0 = (size_t)r * 2 * K + kv * 8;
    *(uint4*)(dst + e0)     = hi.v;
    *(uint4*)(dst + e0 + K) = lo.v;
}

__global__ void pre_A2_kernel(const float* __restrict__ w2) {
    int idx = blockIdx.x * blockDim.x + threadIdx.x;  // 512*512*4
    int q = idx & 3;
    int cf = idx >> 2;
    int f = cf & 511;
    int c = cf >> 9;
    int ip = q >> 1, jp = q & 1;
    const float* wb = w2 + (size_t)(c * 512 + f) * 9;
    float s = 0.f;
    #pragma unroll
    for (int i = 0; i < 2; i++)
        #pragma unroll
        for (int j = 0; j < 2; j++)
            s += wb[(ip - i + 1) * 3 + (jp - j + 1)];
    unsigned short hi, lo;
    split_hi_lo(0.25f * s, hi, lo);
    size_t e0 = (size_t)c * 4096 + f * 4 + q;
    g_A23[e0]        = hi;
    g_A23[e0 + 2048] = lo;
}

// conv B: W3[n=t*512+c][di*512+f], fp16 hi only, row stride 1536
__global__ void build_w3_kernel(const float* __restrict__ c1w) {
    int idx = blockIdx.x * blockDim.x + threadIdx.x;   // 1536*3*64
    int fg = idx & 63;
    int di = (idx >> 6) % 3;
    int n  = idx / 192;
    int t = n >> 9, c = n & 511;
    Pack8 hi;
    #pragma unroll
    for (int j = 0; j < 8; j++) {
        int f = fg * 8 + j;
        size_t base = ((size_t)(c * 512 + f) * 3 + di) * 3;
        float w;
        if (t == 0)      w = c1w[base] + c1w[base + 1] + c1w[base + 2];
        else if (t == 1) w = c1w[base];
        else             w = c1w[base + 2];
        hi.s[j] = __half_as_ushort(__float2half_rn(w));
    }
    *(uint4*)(g_W3 + (size_t)n * 1536 + di * 512 + fg * 8) = hi.v;
}

// ---------------- unified HMMA GEMM ----------------
// MODE 0 (conv): 1-term fp16. A read from vaT16 with di-shifted rows
//   (di = chunk>>4; src row = b*8+i+di-1; zero page when OOB). B = W3, stride Ks.
// MODE 1 (G3): 3-term, relu(acc+bias) -> float out.
// MODE 2 (G1): TERMS-term, h3 deduped split store.
// MODE 3 (G2): 3-term, vaT16 fp16 epilogue: vx*relu(acc+bias).
template <int TM, int MODE, int TERMS>
__global__ void __launch_bounds__((TM == 256) ? 512 : 256, (TM == 256) ? 1 : 2)
hmma_kernel(const unsigned short* __restrict__ A, const unsigned short* __restrict__ Bm,
            const float* __restrict__ bias, float* __restrict__ outF,
            unsigned short* __restrict__ outH, const float* __restrict__ vx,
            int Ks, int ldc, size_t batchA, size_t batchB, int batchBias)
{
    constexpr int THREADS = (TM == 256) ? 512 : 256;
    constexpr int ROWS = TM + 128;
    constexpr int CH = ROWS * 4 / THREADS;
    constexpr int WMC = TM / 64;
    constexpr int ABUF = TM * LDK;
    constexpr int BBUF = 128 * LDK;

    extern __shared__ __align__(16) unsigned short smem[];
    unsigned short* sA = smem;                 // [2][ABUF]
    unsigned short* sB = smem + 2 * ABUF;      // [2][BBUF]

    const int tid = threadIdx.x;
    const int wid = tid >> 5, lane = tid & 31;
    const int m0 = blockIdx.y * TM;
    const int n0 = blockIdx.x * 128;
    const int z  = blockIdx.z;
    const int wm = (wid % WMC) * 64;
    const int wn = (wid / WMC) * 32;

    const int SK_A = (MODE == 0) ? 512 : ((TERMS == 3) ? (2 * Ks) / 3 : Ks);
    const int SK_B = (MODE == 0) ? Ks : SK_A;
    const int NIT = Ks / 32;
    const int nb = (TERMS == 3) ? NIT / 3 : NIT / 2;

    A  += (size_t)z * batchA;
    Bm += (size_t)z * batchB;
    if (MODE >= 1) bias += (size_t)z * batchBias;

    // staging maps (cp.async)
    const unsigned short* gp[CH];
    uint32_t sdA[CH];
    bool isA_[CH];
    int irow[CH];   // i = row & 7 (conv shift mode)
    #pragma unroll
    for (int t = 0; t < CH; t++) {
        int id = tid + t * THREADS;
        int r = id >> 2, q = id & 3;
        if (r < TM) {
            gp[t] = A + (size_t)(m0 + r) * SK_A + q * 8;
            sdA[t] = smem_u32(sA + r * LDK + q * 8);
            isA_[t] = true;
            irow[t] = r & 7;
        } else {
            gp[t] = Bm + (size_t)(n0 + r - TM) * SK_B + q * 8;
            sdA[t] = smem_u32(sB + (r - TM) * LDK + q * 8);
            isA_[t] = false;
            irow[t] = 0;
        }
    }

    float acc[4][4][4];
    #pragma unroll
    for (int i = 0; i < 4; i++)
        #pragma unroll
        for (int j = 0; j < 4; j++)
            #pragma unroll
            for (int q = 0; q < 4; q++) acc[i][j][q] = 0.f;

    const uint32_t sA_base = smem_u32(sA);
    const uint32_t sB_base = smem_u32(sB);
    const int aRow = wm + (lane & 15);
    const int aKof = (lane >> 4) * 8;
    const int bRow = wn + ((lane & 7) | ((lane >> 4) << 3));
    const int bKof = ((lane >> 3) & 1) * 8;

    // stage logical chunk k into buffer buf
    auto stage = [&](int k, int buf) {
        if (MODE == 0) {
            const int di = k >> 4;                      // 0,1,2
            const int ao = (di - 1) * 512 + (k & 15) * 32;
            #pragma unroll
            for (int t = 0; t < CH; t++) {
                const unsigned short* src;
                if (isA_[t]) {
                    int ii = irow[t] + di;              // valid if 1..8
                    src = (ii >= 1 && ii <= 8) ? gp[t] + ao : g_zero;
                } else {
                    src = gp[t] + (size_t)k * 32;
                }
                uint32_t dst = sdA[t] + (uint32_t)buf * (isA_[t] ? ABUF : BBUF) * 2;
                cp_async16(dst, src);
            }
        } else {
            int kA = (TERMS == 3) ? ((k < 2 * nb) ? k : k - 2 * nb) : k;
            int kB = (k < nb) ? k : k - nb;
            #pragma unroll
            for (int t = 0; t < CH; t++) {
                const unsigned short* src = gp[t] + (size_t)(isA_[t] ? kA : kB) * 32;
                uint32_t dst = sdA[t] + (uint32_t)buf * (isA_[t] ? ABUF : BBUF) * 2;
                cp_async16(dst, src);
            }
        }
        CP_COMMIT();
    };

    stage(0, 0);
    CP_WAIT0();
    __syncthreads();

    for (int it = 0; it < NIT; it++) {
        const int cur = it & 1;
        const bool more = (it + 1) < NIT;
        if (more) stage(it + 1, cur ^ 1);

        const uint32_t aBuf = sA_base + cur * (ABUF * 2);
        const uint32_t bBuf = sB_base + cur * (BBUF * 2);
        #pragma unroll
        for (int ks = 0; ks < 32; ks += 16) {
            uint32_t af[4][4], bf[4][2];
            #pragma unroll
            for (int mt = 0; mt < 4; mt++)
                ldmatrix_x4(af[mt][0], af[mt][1], af[mt][2], af[mt][3],
                            aBuf + (uint32_t)(((aRow + mt * 16) * LDK + ks + aKof) * 2));
            #pragma unroll
            for (int np = 0; np < 2; np++)
                ldmatrix_x4(bf[np * 2][0], bf[np * 2][1], bf[np * 2 + 1][0], bf[np * 2 + 1][1],
                            bBuf + (uint32_t)(((bRow + np * 16) * LDK + ks + bKof) * 2));
            #pragma unroll
            for (int mt = 0; mt < 4; mt++)
                #pragma unroll
                for (int nt = 0; nt < 4; nt++)
                    mma_16816(acc[mt][nt], af[mt], bf[nt]);
        }
        if (more) CP_WAIT0();
        __syncthreads();
    }

    // epilogue
    const int erow = lane >> 2;
    const int ecol = (lane & 3) * 2;
    #pragma unroll
    for (int mt = 0; mt < 4; mt++) {
        #pragma unroll
        for (int nt = 0; nt < 4; nt++) {
            const int r0 = m0 + wm + mt * 16 + erow;
            const int c  = n0 + wn + nt * 8 + ecol;
            const float* v = acc[mt][nt];
            if (MODE == 0) {
                *(float2*)&outF[(size_t)r0 * ldc + c] = make_float2(v[0], v[1]);
                *(float2*)&outF[(size_t)(r0 + 8) * ldc + c] = make_float2(v[2], v[3]);
            } else if (MODE == 1) {
                float b0 = bias[c], b1 = bias[c + 1];
                *(float2*)&outF[(size_t)r0 * ldc + c] =
                    make_float2(fmaxf(v[0] + b0, 0.f), fmaxf(v[1] + b1, 0.f));
                *(float2*)&outF[(size_t)(r0 + 8) * ldc + c] =
                    make_float2(fmaxf(v[2] + b0, 0.f), fmaxf(v[3] + b1, 0.f));
            } else if (MODE == 2) {
                float b0 = bias[c], b1 = bias[c + 1];
                int zz = c >> 9, f = c & 511;
                #pragma unroll
                for (int hr = 0; hr < 2; hr++) {
                    float y0 = fmaxf(v[hr * 2] + b0, 0.f);
                    float y1 = fmaxf(v[hr * 2 + 1] + b1, 0.f);
                    unsigned short h0, l0, h1, l1;
                    split_hi_lo(y0, h0, l0);
                    split_hi_lo(y1, h1, l1);
                    uint32_t hip = (uint32_t)h0 | ((uint32_t)h1 << 16);
                    uint32_t lop = (uint32_t)l0 | ((uint32_t)l1 << 16);
                    size_t base = ((size_t)zz * 1024 + (r0 + hr * 8)) * 1024 + f;
                    *(uint32_t*)&outH[base]       = hip;
                    *(uint32_t*)&outH[base + 512] = lop;
                }
            } else {  // MODE 3: fp16 vaT epilogue
                float b0 = bias[c], b1 = bias[c + 1];
                #pragma unroll
                for (int hr = 0; hr < 2; hr++) {
                    int r = r0 + hr * 8;
                    float s0 = vx[(size_t)r * 512 + c];
                    float s1 = vx[(size_t)r * 512 + c + 1];
                    float y0 = s0 * fmaxf(v[hr * 2] + b0, 0.f);
                    float y1 = s1 * fmaxf(v[hr * 2 + 1] + b1, 0.f);
                    uint32_t pk = (uint32_t)__half_as_ushort(__float2half_rn(y0))
                                | ((uint32_t)__half_as_ushort(__float2half_rn(y1)) << 16);
                    *(uint32_t*)&outH[((size_t)r * 8 + z) * 512 + c] = pk;
                }
            }
        }
    }
}

// ---------------- pool: Y -> p3 (deduped split) ----------------
__global__ void pool_split_kernel(const float* __restrict__ Y, const float* __restrict__ c1b) {
    int idx = blockIdx.x * blockDim.x + threadIdx.x;   // 1024*512
    int c = idx & 511, b = idx >> 9;
    float bias = c1b[c];
    float m00 = -1e30f, m01 = -1e30f, m10 = -1e30f, m11 = -1e30f;
    #pragma unroll
    for (int i = 0; i < 8; i++) {
        size_t base = (size_t)(b * 8 + i) * 1536;
        float yM = Y[base + c];
        float yB = Y[base + 512 + c];
        float yC = Y[base + 1024 + c];
        float vL = fmaxf(yM - yB, yM);
        float vR = fmaxf(yM - yC, yM);
        if (i < 4) { m00 = fmaxf(m00, vL); m01 = fmaxf(m01, vR); }
        else       { m10 = fmaxf(m10, vL); m11 = fmaxf(m11, vR); }
    }
    float p[4] = {m00 + bias, m01 + bias, m10 + bias, m11 + bias};
    ushort4 hi, lo;
    split_hi_lo(p[0], hi.x, lo.x);
    split_hi_lo(p[1], hi.y, lo.y);
    split_hi_lo(p[2], hi.z, lo.z);
    split_hi_lo(p[3], hi.w, lo.w);
    size_t e0 = (size_t)b * 4096 + c * 4;
    *(ushort4*)(g_p3 + e0)        = hi;
    *(ushort4*)(g_p3 + e0 + 2048) = lo;
}

// ---------------- launch ----------------
extern "C" void kernel_launch(void* const* d_in, const int* in_sizes, int n_in,
                              void* d_out, int out_size) {
    (void)in_sizes; (void)n_in; (void)out_size;
    const float* vx  = (const float*)d_in[0];
    const float* ax  = (const float*)d_in[1];
    const float* W1  = (const float*)d_in[2];
    const float* b1  = (const float*)d_in[3];
    const float* W2  = (const float*)d_in[4];
    const float* b2  = (const float*)d_in[5];
    const float* c1w = (const float*)d_in[6];
    const float* c1b = (const float*)d_in[7];
    const float* c2w = (const float*)d_in[8];
    const float* c2b = (const float*)d_in[9];
    float* out = (float*)d_out;

    void *p_xcat3, *p_W13, *p_h3, *p_W23, *p_vaT16, *p_W3, *p_Y, *p_p3, *p_A23;
    cudaGetSymbolAddress(&p_xcat3, g_xcat3);
    cudaGetSymbolAddress(&p_W13,   g_W13);
    cudaGetSymbolAddress(&p_h3,    g_h3);
    cudaGetSymbolAddress(&p_W23,   g_W23);
    cudaGetSymbolAddress(&p_vaT16, g_vaT16);
    cudaGetSymbolAddress(&p_W3,    g_W3);
    cudaGetSymbolAddress(&p_Y,     g_Y);
    cudaGetSymbolAddress(&p_p3,    g_p3);
    cudaGetSymbolAddress(&p_A23,   g_A23);

    const int SM256 = (2 * 256 + 2 * 128) * LDK * 2;  // 61440
    const int SM128 = (2 * 128 + 2 * 128) * LDK * 2;  // 40960
    cudaFuncSetAttribute((const void*)hmma_kernel<256, 0, 1>, cudaFuncAttributeMaxDynamicSharedMemorySize, SM256);
    cudaFuncSetAttribute((const void*)hmma_kernel<256, 2, 2>, cudaFuncAttributeMaxDynamicSharedMemorySize, SM256);
    cudaFuncSetAttribute((const void*)hmma_kernel<256, 3, 3>, cudaFuncAttributeMaxDynamicSharedMemorySize, SM256);
    cudaFuncSetAttribute((const void*)hmma_kernel<128, 1, 3>, cudaFuncAttributeMaxDynamicSharedMemorySize, SM128);

    // operand builders
    concat_split_kernel<<<512, 256>>>(vx, ax);                              // xcat3
    split3B_kernel<<<2048, 256>>>(W1, (unsigned short*)p_W13, 128, 1024);   // W1 split
    split3B_kernel<<<1024, 256>>>(W2, (unsigned short*)p_W23, 64, 512);     // W2 split
    pre_A2_kernel<<<4096, 256>>>(c2w);                                      // A2 split
    build_w3_kernel<<<1152, 256>>>(c1w);                                    // W3 (fp16 hi)

    // GEMM1 (2-term): h3 = split(relu(xcat*W1^T + b1)); logical K=2048
    hmma_kernel<256, 2, 2><<<dim3(32, 4), 512, SM256>>>(
        (const unsigned short*)p_xcat3, (const unsigned short*)p_W13, b1,
        nullptr, (unsigned short*)p_h3, nullptr, 2048, 0, 0, 0, 0);

    // GEMM2 (3-term, batch z): vaT16 = fp16(vx*relu(h_z*W2_z^T + b2_z)); K=1536
    hmma_kernel<256, 3, 3><<<dim3(4, 4, 8), 512, SM256>>>(
        (const unsigned short*)p_h3, (const unsigned short*)p_W23, b2,
        nullptr, (unsigned short*)p_vaT16, vx, 1536, 0,
        (size_t)1024 * 1024, (size_t)512 * 1024, 512);

    // conv (1-term, shifted A from vaT16): Y = X*W3^T; logical K=1536
    hmma_kernel<256, 0, 1><<<dim3(12, 32), 512, SM256>>>(
        (const unsigned short*)p_vaT16, (const unsigned short*)p_W3, nullptr,
        (float*)p_Y, nullptr, nullptr, 1536, 1536, 0, 0, 0);

    // pool -> p3
    pool_split_kernel<<<2048, 256>>>((const float*)p_Y, c1b);

    // GEMM3 (3-term): out = relu(p*A2^T + c2b); logical K=6144
    hmma_kernel<128, 1, 3><<<dim3(4, 8), 256, SM128>>>(
        (const unsigned short*)p_p3, (const unsigned short*)p_A23, c2b,
        out, nullptr, nullptr, 6144, 512, 0, 0, 0);
}

// round 10
// speedup vs baseline: 1.4738x; 1.4738x over previous
#include <cuda_runtime.h>
#include <cuda_fp16.h>
#include <cstdint>
#include <cstddef>

// B=1024, F=512, N=8 — HMMA fp16 (fp32 accum), split-precision where needed.
// G1: 2-term. G2/G3: 3-term. conv: 1-term fp16 with a materialized fp16 gather
// operand (g_X16) so the GEMM staging loop stays uniform/coalesced (the R9
// in-stage shift gather regressed 2x; reverted).

#define LDK 40   // smem row stride in halves (80B, conflict-free ldmatrix)

// ---------------- static scratch ----------------
__device__ unsigned short g_xcat3[(size_t)1024 * 2048];   // A-split of [vx|ax]
__device__ unsigned short g_W13[(size_t)4096 * 2048];     // B-split of W1
__device__ unsigned short g_h3[(size_t)8 * 1024 * 1024];  // [z][b][hi512|lo512]
__device__ unsigned short g_W23[(size_t)4096 * 1024];     // B-split of W2
__device__ unsigned short g_vaT16[(size_t)1024 * 8 * 512];// fp16 va, [b][i][f]
__device__ unsigned short g_X16[(size_t)8192 * 1536];     // conv A, fp16 (di-shifted)
__device__ unsigned short g_W3[(size_t)1536 * 1536];      // conv B, fp16
__device__ float g_Y[(size_t)8192 * 1536];                // conv out
__device__ unsigned short g_p3[(size_t)1024 * 4096];      // pooled split
__device__ unsigned short g_A23[(size_t)512 * 4096];      // conv2-collapsed split

// ---------------- helpers ----------------
union Pack8 { unsigned short s[8]; uint4 v; };
__device__ __forceinline__ void split_hi_lo(float x, unsigned short& hi, unsigned short& lo) {
    __half h = __float2half_rn(x);
    float hf = __half2float(h);
    __half l = __float2half_rn(x - hf);
    hi = __half_as_ushort(h);
    lo = __half_as_ushort(l);
}
__device__ __forceinline__ uint32_t smem_u32(const void* p) {
    uint32_t a;
    asm("{ .reg .u64 t; cvta.to.shared.u64 t, %1; cvt.u32.u64 %0, t; }" : "=r"(a) : "l"(p));
    return a;
}
__device__ __forceinline__ void ldmatrix_x4(uint32_t& r0, uint32_t& r1, uint32_t& r2, uint32_t& r3,
                                            uint32_t addr) {
    asm volatile("ldmatrix.sync.aligned.m8n8.x4.shared.b16 {%0,%1,%2,%3}, [%4];"
                 : "=r"(r0), "=r"(r1), "=r"(r2), "=r"(r3) : "r"(addr));
}
__device__ __forceinline__ void mma_16816(float* c, const uint32_t* a, const uint32_t* b) {
    asm volatile("mma.sync.aligned.m16n8k16.row.col.f32.f16.f16.f32 "
                 "{%0,%1,%2,%3}, {%4,%5,%6,%7}, {%8,%9}, {%0,%1,%2,%3};"
                 : "+f"(c[0]), "+f"(c[1]), "+f"(c[2]), "+f"(c[3])
                 : "r"(a[0]), "r"(a[1]), "r"(a[2]), "r"(a[3]), "r"(b[0]), "r"(b[1]));
}
__device__ __forceinline__ void cp_async16(uint32_t dst, const void* src) {
    asm volatile("cp.async.cg.shared.global [%0], [%1], 16;" :: "r"(dst), "l"(src));
}
#define CP_COMMIT() asm volatile("cp.async.commit_group;" ::: "memory")
#define CP_WAIT0()  asm volatile("cp.async.wait_group 0;" ::: "memory")

// ---------------- operand builders ----------------
__global__ void concat_split_kernel(const float* __restrict__ vx, const float* __restrict__ ax) {
    int idx = blockIdx.x * blockDim.x + threadIdx.x;  // 1024*128
    int kv = idx & 127, b = idx >> 7;
    const float* src = (kv < 64) ? (vx + (size_t)b * 512 + kv * 8)
                                 : (ax + (size_t)b * 512 + (kv - 64) * 8);
    float4 x0 = *(const float4*)src, x1 = *(const float4*)(src + 4);
    float vals[8] = {x0.x, x0.y, x0.z, x0.w, x1.x, x1.y, x1.z, x1.w};
    Pack8 hi, lo;
    #pragma unroll
    for (int j = 0; j < 8; j++) split_hi_lo(vals[j], hi.s[j], lo.s[j]);
    size_t e0 = (size_t)b * 2048 + kv * 8;
    *(uint4*)(g_xcat3 + e0)        = hi.v;
    *(uint4*)(g_xcat3 + e0 + 1024) = lo.v;
}

__global__ void split3B_kernel(const float* __restrict__ src, unsigned short* __restrict__ dst,
                               int Kv /* K/8 */, int K) {
    int idx = blockIdx.x * blockDim.x + threadIdx.x;  // R*Kv
    int kv = idx % Kv, r = idx / Kv;
    const float* s = src + (size_t)r * K + kv * 8;
    float4 x0 = *(const float4*)s, x1 = *(const float4*)(s + 4);
    float vals[8] = {x0.x, x0.y, x0.z, x0.w, x1.x, x1.y, x1.z, x1.w};
    Pack8 hi, lo;
    #pragma unroll
    for (int j = 0; j < 8; j++) split_hi_lo(vals[j], hi.s[j], lo.s[j]);
    size_t e0 = (size_t)r * 2 * K + kv * 8;
    *(uint4*)(dst + e0)     = hi.v;
    *(uint4*)(dst + e0 + K) = lo.v;
}

__global__ void pre_A2_kernel(const float* __restrict__ w2) {
    int idx = blockIdx.x * blockDim.x + threadIdx.x;  // 512*512*4
    int q = idx & 3;
    int cf = idx >> 2;
    int f = cf & 511;
    int c = cf >> 9;
    int ip = q >> 1, jp = q & 1;
    const float* wb = w2 + (size_t)(c * 512 + f) * 9;
    float s = 0.f;
    #pragma unroll
    for (int i = 0; i < 2; i++)
        #pragma unroll
        for (int j = 0; j < 2; j++)
            s += wb[(ip - i + 1) * 3 + (jp - j + 1)];
    unsigned short hi, lo;
    split_hi_lo(0.25f * s, hi, lo);
    size_t e0 = (size_t)c * 4096 + f * 4 + q;
    g_A23[e0]        = hi;
    g_A23[e0 + 2048] = lo;
}

// conv B: W3[n=t*512+c][di*512+f], fp16, row stride 1536
__global__ void build_w3_kernel(const float* __restrict__ c1w) {
    int idx = blockIdx.x * blockDim.x + threadIdx.x;   // 1536*3*64
    int fg = idx & 63;
    int di = (idx >> 6) % 3;
    int n  = idx / 192;
    int t = n >> 9, c = n & 511;
    Pack8 hi;
    #pragma unroll
    for (int j = 0; j < 8; j++) {
        int f = fg * 8 + j;
        size_t base = ((size_t)(c * 512 + f) * 3 + di) * 3;
        float w;
        if (t == 0)      w = c1w[base] + c1w[base + 1] + c1w[base + 2];
        else if (t == 1) w = c1w[base];
        else             w = c1w[base + 2];
        hi.s[j] = __half_as_ushort(__float2half_rn(w));
    }
    *(uint4*)(g_W3 + (size_t)n * 1536 + di * 512 + fg * 8) = hi.v;
}

// conv A: pure fp16 gather, X16[r=(b,i)][di*512+f] = vaT16[b][i+di-1][f] (0 if OOB)
__global__ void build_x16_kernel() {
    int idx = blockIdx.x * blockDim.x + threadIdx.x;   // 8192*3*64
    int fg = idx & 63;
    int di = (idx >> 6) % 3;
    int r  = idx / 192;
    int b = r >> 3, i = r & 7;
    int src = i + di - 1;
    uint4 v = make_uint4(0, 0, 0, 0);
    if (src >= 0 && src < 8)
        v = *(const uint4*)(g_vaT16 + ((size_t)(b * 8 + src) * 512) + fg * 8);
    *(uint4*)(g_X16 + (size_t)r * 1536 + di * 512 + fg * 8) = v;
}

// ---------------- unified HMMA GEMM ----------------
// TERMS==3: stored [hi|lo] stride 2Ks/3; A logical [hi|lo|hi], B [hi|hi|lo].
// TERMS==2: stored stride Ks; A logical [hi|lo] (kA=k), B [hi|hi] (kB remap).
// TERMS==1: plain GEMM, stride Ks, kA=kB=k.
// MODE 0: outF = acc (conv->Y)   MODE 1: relu(acc+bias) (G3->out)
// MODE 2: h3 deduped split store (G1)   MODE 3: vaT16 fp16 epilogue (G2)
template <int TM, int MODE, int TERMS>
__global__ void __launch_bounds__((TM == 256) ? 512 : 256, (TM == 256) ? 1 : 2)
hmma_kernel(const unsigned short* __restrict__ A, const unsigned short* __restrict__ Bm,
            const float* __restrict__ bias, float* __restrict__ outF,
            unsigned short* __restrict__ outH, const float* __restrict__ vx,
            int Ks, int ldc, size_t batchA, size_t batchB, int batchBias)
{
    constexpr int THREADS = (TM == 256) ? 512 : 256;
    constexpr int ROWS = TM + 128;
    constexpr int CH = ROWS * 4 / THREADS;
    constexpr int WMC = TM / 64;
    constexpr int ABUF = TM * LDK;
    constexpr int BBUF = 128 * LDK;

    extern __shared__ __align__(16) unsigned short smem[];
    unsigned short* sA = smem;                 // [2][ABUF]
    unsigned short* sB = smem + 2 * ABUF;      // [2][BBUF]

    const int tid = threadIdx.x;
    const int wid = tid >> 5, lane = tid & 31;
    const int m0 = blockIdx.y * TM;
    const int n0 = blockIdx.x * 128;
    const int z  = blockIdx.z;
    const int wm = (wid % WMC) * 64;
    const int wn = (wid / WMC) * 32;

    const int SK = (TERMS == 3) ? (2 * Ks) / 3 : Ks;   // stored row stride
    const int NIT = Ks / 32;
    const int nb = (TERMS == 3) ? NIT / 3 : NIT / 2;

    A  += (size_t)z * batchA;
    Bm += (size_t)z * batchB;
    if (MODE >= 1) bias += (size_t)z * batchBias;

    // staging maps (cp.async)
    const unsigned short* gp[CH];
    uint32_t sdA[CH];
    bool isA_[CH];
    #pragma unroll
    for (int t = 0; t < CH; t++) {
        int id = tid + t * THREADS;
        int r = id >> 2, q = id & 3;
        if (r < TM) {
            gp[t] = A + (size_t)(m0 + r) * SK + q * 8;
            sdA[t] = smem_u32(sA + r * LDK + q * 8);
            isA_[t] = true;
        } else {
            gp[t] = Bm + (size_t)(n0 + r - TM) * SK + q * 8;
            sdA[t] = smem_u32(sB + (r - TM) * LDK + q * 8);
            isA_[t] = false;
        }
    }

    float acc[4][4][4];
    #pragma unroll
    for (int i = 0; i < 4; i++)
        #pragma unroll
        for (int j = 0; j < 4; j++)
            #pragma unroll
            for (int q = 0; q < 4; q++) acc[i][j][q] = 0.f;

    const uint32_t sA_base = smem_u32(sA);
    const uint32_t sB_base = smem_u32(sB);
    const int aRow = wm + (lane & 15);
    const int aKof = (lane >> 4) * 8;
    const int bRow = wn + ((lane & 7) | ((lane >> 4) << 3));
    const int bKof = ((lane >> 3) & 1) * 8;

    // stage logical chunk k into buffer buf (uniform for all threads)
    auto stage = [&](int k, int buf) {
        int kA, kB;
        if (TERMS == 3)      { kA = (k < 2 * nb) ? k : k - 2 * nb; kB = (k < nb) ? k : k - nb; }
        else if (TERMS == 2) { kA = k;                             kB = (k < nb) ? k : k - nb; }
        else                 { kA = k;                             kB = k; }
        #pragma unroll
        for (int t = 0; t < CH; t++) {
            const unsigned short* src = gp[t] + (size_t)(isA_[t] ? kA : kB) * 32;
            uint32_t dst = sdA[t] + (uint32_t)buf * (isA_[t] ? ABUF : BBUF) * 2;
            cp_async16(dst, src);
        }
        CP_COMMIT();
    };

    stage(0, 0);
    CP_WAIT0();
    __syncthreads();

    for (int it = 0; it < NIT; it++) {
        const int cur = it & 1;
        const bool more = (it + 1) < NIT;
        if (more) stage(it + 1, cur ^ 1);

        const uint32_t aBuf = sA_base + cur * (ABUF * 2);
        const uint32_t bBuf = sB_base + cur * (BBUF * 2);
        #pragma unroll
        for (int ks = 0; ks < 32; ks += 16) {
            uint32_t af[4][4], bf[4][2];
            #pragma unroll
            for (int mt = 0; mt < 4; mt++)
                ldmatrix_x4(af[mt][0], af[mt][1], af[mt][2], af[mt][3],
                            aBuf + (uint32_t)(((aRow + mt * 16) * LDK + ks + aKof) * 2));
            #pragma unroll
            for (int np = 0; np < 2; np++)
                ldmatrix_x4(bf[np * 2][0], bf[np * 2][1], bf[np * 2 + 1][0], bf[np * 2 + 1][1],
                            bBuf + (uint32_t)(((bRow + np * 16) * LDK + ks + bKof) * 2));
            #pragma unroll
            for (int mt = 0; mt < 4; mt++)
                #pragma unroll
                for (int nt = 0; nt < 4; nt++)
                    mma_16816(acc[mt][nt], af[mt], bf[nt]);
        }
        if (more) CP_WAIT0();
        __syncthreads();
    }

    // epilogue
    const int erow = lane >> 2;
    const int ecol = (lane & 3) * 2;
    #pragma unroll
    for (int mt = 0; mt < 4; mt++) {
        #pragma unroll
        for (int nt = 0; nt < 4; nt++) {
            const int r0 = m0 + wm + mt * 16 + erow;
            const int c  = n0 + wn + nt * 8 + ecol;
            const float* v = acc[mt][nt];
            if (MODE == 0) {
                *(float2*)&outF[(size_t)r0 * ldc + c] = make_float2(v[0], v[1]);
                *(float2*)&outF[(size_t)(r0 + 8) * ldc + c] = make_float2(v[2], v[3]);
            } else if (MODE == 1) {
                float b0 = bias[c], b1 = bias[c + 1];
                *(float2*)&outF[(size_t)r0 * ldc + c] =
                    make_float2(fmaxf(v[0] + b0, 0.f), fmaxf(v[1] + b1, 0.f));
                *(float2*)&outF[(size_t)(r0 + 8) * ldc + c] =
                    make_float2(fmaxf(v[2] + b0, 0.f), fmaxf(v[3] + b1, 0.f));
            } else if (MODE == 2) {
                float b0 = bias[c], b1 = bias[c + 1];
                int zz = c >> 9, f = c & 511;
                #pragma unroll
                for (int hr = 0; hr < 2; hr++) {
                    float y0 = fmaxf(v[hr * 2] + b0, 0.f);
                    float y1 = fmaxf(v[hr * 2 + 1] + b1, 0.f);
                    unsigned short h0, l0, h1, l1;
                    split_hi_lo(y0, h0, l0);
                    split_hi_lo(y1, h1, l1);
                    uint32_t hip = (uint32_t)h0 | ((uint32_t)h1 << 16);
                    uint32_t lop = (uint32_t)l0 | ((uint32_t)l1 << 16);
                    size_t base = ((size_t)zz * 1024 + (r0 + hr * 8)) * 1024 + f;
                    *(uint32_t*)&outH[base]       = hip;
                    *(uint32_t*)&outH[base + 512] = lop;
                }
            } else {  // MODE 3: fp16 vaT epilogue
                float b0 = bias[c], b1 = bias[c + 1];
                #pragma unroll
                for (int hr = 0; hr < 2; hr++) {
                    int r = r0 + hr * 8;
                    float s0 = vx[(size_t)r * 512 + c];
                    float s1 = vx[(size_t)r * 512 + c + 1];
                    float y0 = s0 * fmaxf(v[hr * 2] + b0, 0.f);
                    float y1 = s1 * fmaxf(v[hr * 2 + 1] + b1, 0.f);
                    uint32_t pk = (uint32_t)__half_as_ushort(__float2half_rn(y0))
                                | ((uint32_t)__half_as_ushort(__float2half_rn(y1)) << 16);
                    *(uint32_t*)&outH[((size_t)r * 8 + z) * 512 + c] = pk;
                }
            }
        }
    }
}

// ---------------- pool: Y -> p3 (deduped split) ----------------
__global__ void pool_split_kernel(const float* __restrict__ Y, const float* __restrict__ c1b) {
    int idx = blockIdx.x * blockDim.x + threadIdx.x;   // 1024*512
    int c = idx & 511, b = idx >> 9;
    float bias = c1b[c];
    float m00 = -1e30f, m01 = -1e30f, m10 = -1e30f, m11 = -1e30f;
    #pragma unroll
    for (int i = 0; i < 8; i++) {
        size_t base = (size_t)(b * 8 + i) * 1536;
        float yM = Y[base + c];
        float yB = Y[base + 512 + c];
        float yC = Y[base + 1024 + c];
        float vL = fmaxf(yM - yB, yM);
        float vR = fmaxf(yM - yC, yM);
        if (i < 4) { m00 = fmaxf(m00, vL); m01 = fmaxf(m01, vR); }
        else       { m10 = fmaxf(m10, vL); m11 = fmaxf(m11, vR); }
    }
    float p[4] = {m00 + bias, m01 + bias, m10 + bias, m11 + bias};
    ushort4 hi, lo;
    split_hi_lo(p[0], hi.x, lo.x);
    split_hi_lo(p[1], hi.y, lo.y);
    split_hi_lo(p[2], hi.z, lo.z);
    split_hi_lo(p[3], hi.w, lo.w);
    size_t e0 = (size_t)b * 4096 + c * 4;
    *(ushort4*)(g_p3 + e0)        = hi;
    *(ushort4*)(g_p3 + e0 + 2048) = lo;
}

// ---------------- launch ----------------
extern "C" void kernel_launch(void* const* d_in, const int* in_sizes, int n_in,
                              void* d_out, int out_size) {
    (void)in_sizes; (void)n_in; (void)out_size;
    const float* vx  = (const float*)d_in[0];
    const float* ax  = (const float*)d_in[1];
    const float* W1  = (const float*)d_in[2];
    const float* b1  = (const float*)d_in[3];
    const float* W2  = (const float*)d_in[4];
    const float* b2  = (const float*)d_in[5];
    const float* c1w = (const float*)d_in[6];
    const float* c1b = (const float*)d_in[7];
    const float* c2w = (const float*)d_in[8];
    const float* c2b = (const float*)d_in[9];
    float* out = (float*)d_out;

    void *p_xcat3, *p_W13, *p_h3, *p_W23, *p_vaT16, *p_X16, *p_W3, *p_Y, *p_p3, *p_A23;
    cudaGetSymbolAddress(&p_xcat3, g_xcat3);
    cudaGetSymbolAddress(&p_W13,   g_W13);
    cudaGetSymbolAddress(&p_h3,    g_h3);
    cudaGetSymbolAddress(&p_W23,   g_W23);
    cudaGetSymbolAddress(&p_vaT16, g_vaT16);
    cudaGetSymbolAddress(&p_X16,   g_X16);
    cudaGetSymbolAddress(&p_W3,    g_W3);
    cudaGetSymbolAddress(&p_Y,     g_Y);
    cudaGetSymbolAddress(&p_p3,    g_p3);
    cudaGetSymbolAddress(&p_A23,   g_A23);

    const int SM256 = (2 * 256 + 2 * 128) * LDK * 2;  // 61440
    const int SM128 = (2 * 128 + 2 * 128) * LDK * 2;  // 40960
    cudaFuncSetAttribute((const void*)hmma_kernel<256, 0, 1>, cudaFuncAttributeMaxDynamicSharedMemorySize, SM256);
    cudaFuncSetAttribute((const void*)hmma_kernel<256, 2, 2>, cudaFuncAttributeMaxDynamicSharedMemorySize, SM256);
    cudaFuncSetAttribute((const void*)hmma_kernel<256, 3, 3>, cudaFuncAttributeMaxDynamicSharedMemorySize, SM256);
    cudaFuncSetAttribute((const void*)hmma_kernel<128, 1, 3>, cudaFuncAttributeMaxDynamicSharedMemorySize, SM128);

    // operand builders
    concat_split_kernel<<<512, 256>>>(vx, ax);                              // xcat3
    split3B_kernel<<<2048, 256>>>(W1, (unsigned short*)p_W13, 128, 1024);   // W1 split
    split3B_kernel<<<1024, 256>>>(W2, (unsigned short*)p_W23, 64, 512);     // W2 split
    pre_A2_kernel<<<4096, 256>>>(c2w);                                      // A2 split
    build_w3_kernel<<<1152, 256>>>(c1w);                                    // W3 (fp16)

    // GEMM1 (2-term): h3 = split(relu(xcat*W1^T + b1)); logical K=2048
    hmma_kernel<256, 2, 2><<<dim3(32, 4), 512, SM256>>>(
        (const unsigned short*)p_xcat3, (const unsigned short*)p_W13, b1,
        nullptr, (unsigned short*)p_h3, nullptr, 2048, 0, 0, 0, 0);

    // GEMM2 (3-term, batch z): vaT16 = fp16(vx*relu(h_z*W2_z^T + b2_z)); K=1536
    hmma_kernel<256, 3, 3><<<dim3(4, 4, 8), 512, SM256>>>(
        (const unsigned short*)p_h3, (const unsigned short*)p_W23, b2,
        nullptr, (unsigned short*)p_vaT16, vx, 1536, 0,
        (size_t)1024 * 1024, (size_t)512 * 1024, 512);

    // conv A gather (fp16 copy), then conv GEMM (1-term): Y = X16*W3^T; K=1536
    build_x16_kernel<<<6144, 256>>>();
    hmma_kernel<256, 0, 1><<<dim3(12, 32), 512, SM256>>>(
        (const unsigned short*)p_X16, (const unsigned short*)p_W3, nullptr,
        (float*)p_Y, nullptr, nullptr, 1536, 1536, 0, 0, 0);

    // pool -> p3
    pool_split_kernel<<<2048, 256>>>((const float*)p_Y, c1b);

    // GEMM3 (3-term): out = relu(p*A2^T + c2b); logical K=6144
    hmma_kernel<128, 1, 3><<<dim3(4, 8), 256, SM128>>>(
        (const unsigned short*)p_p3, (const unsigned short*)p_A23, c2b,
        out, nullptr, nullptr, 6144, 512, 0, 0, 0);
}

// round 11
// speedup vs baseline: 1.8245x; 1.2379x over previous
#include <cuda_runtime.h>
#include <cuda_fp16.h>
#include <cstdint>
#include <cstddef>

// B=1024, F=512, N=8 — HMMA fp16 (fp32 accum).
// G1: 1-term (fp16 x × fp16 W1). G2: 2-term (exact-h split × W2h).
// conv: 1-term with materialized fp16 gather operand, fp16 Y output.
// G3: 2-term (exact-p split × A2h). Error budget ~5e-4 (5 × 2.4e-4 quadrature).

#define LDK 40   // smem row stride in halves (80B, conflict-free ldmatrix)

// ---------------- static scratch ----------------
__device__ unsigned short g_xcat16[(size_t)1024 * 1024]; // fp16 [vx|ax]
__device__ unsigned short g_W16[(size_t)4096 * 1024];    // fp16 W1
__device__ unsigned short g_h3[(size_t)8 * 1024 * 1024]; // [z][b][hi512|lo512] exact split
__device__ unsigned short g_W23[(size_t)4096 * 1024];    // B-split of W2 ([hi|lo])
__device__ unsigned short g_vaT16[(size_t)1024 * 8 * 512];// fp16 va, [b][i][f]
__device__ unsigned short g_X16[(size_t)8192 * 1536];    // conv A, fp16 (di-shifted)
__device__ unsigned short g_W3[(size_t)1536 * 1536];     // conv B, fp16
__device__ unsigned short g_Y16[(size_t)8192 * 1536];    // conv out, fp16
__device__ unsigned short g_p3[(size_t)1024 * 4096];     // pooled exact split [hi|lo]
__device__ unsigned short g_A23[(size_t)512 * 4096];     // conv2-collapsed split [hi|lo]

// ---------------- helpers ----------------
union Pack8 { unsigned short s[8]; uint4 v; };
__device__ __forceinline__ void split_hi_lo(float x, unsigned short& hi, unsigned short& lo) {
    __half h = __float2half_rn(x);
    float hf = __half2float(h);
    __half l = __float2half_rn(x - hf);
    hi = __half_as_ushort(h);
    lo = __half_as_ushort(l);
}
__device__ __forceinline__ uint32_t smem_u32(const void* p) {
    uint32_t a;
    asm("{ .reg .u64 t; cvta.to.shared.u64 t, %1; cvt.u32.u64 %0, t; }" : "=r"(a) : "l"(p));
    return a;
}
__device__ __forceinline__ void ldmatrix_x4(uint32_t& r0, uint32_t& r1, uint32_t& r2, uint32_t& r3,
                                            uint32_t addr) {
    asm volatile("ldmatrix.sync.aligned.m8n8.x4.shared.b16 {%0,%1,%2,%3}, [%4];"
                 : "=r"(r0), "=r"(r1), "=r"(r2), "=r"(r3) : "r"(addr));
}
__device__ __forceinline__ void mma_16816(float* c, const uint32_t* a, const uint32_t* b) {
    asm volatile("mma.sync.aligned.m16n8k16.row.col.f32.f16.f16.f32 "
                 "{%0,%1,%2,%3}, {%4,%5,%6,%7}, {%8,%9}, {%0,%1,%2,%3};"
                 : "+f"(c[0]), "+f"(c[1]), "+f"(c[2]), "+f"(c[3])
                 : "r"(a[0]), "r"(a[1]), "r"(a[2]), "r"(a[3]), "r"(b[0]), "r"(b[1]));
}
__device__ __forceinline__ void cp_async16(uint32_t dst, const void* src) {
    asm volatile("cp.async.cg.shared.global [%0], [%1], 16;" :: "r"(dst), "l"(src));
}
#define CP_COMMIT() asm volatile("cp.async.commit_group;" ::: "memory")
#define CP_WAIT0()  asm volatile("cp.async.wait_group 0;" ::: "memory")

// ---------------- operand builders ----------------
// [vx|ax] -> plain fp16
__global__ void concat16_kernel(const float* __restrict__ vx, const float* __restrict__ ax) {
    int idx = blockIdx.x * blockDim.x + threadIdx.x;  // 1024*128
    int kv = idx & 127, b = idx >> 7;
    const float* src = (kv < 64) ? (vx + (size_t)b * 512 + kv * 8)
                                 : (ax + (size_t)b * 512 + (kv - 64) * 8);
    float4 x0 = *(const float4*)src, x1 = *(const float4*)(src + 4);
    float vals[8] = {x0.x, x0.y, x0.z, x0.w, x1.x, x1.y, x1.z, x1.w};
    Pack8 h;
    #pragma unroll
    for (int j = 0; j < 8; j++) h.s[j] = __half_as_ushort(__float2half_rn(vals[j]));
    *(uint4*)(g_xcat16 + (size_t)b * 1024 + kv * 8) = h.v;
}

// plain float -> fp16, vectorized (n8 = elements/8)
__global__ void build16_kernel(const float* __restrict__ src, unsigned short* __restrict__ dst,
                               int n8) {
    int idx = blockIdx.x * blockDim.x + threadIdx.x;
    if (idx >= n8) return;
    const float* s = src + (size_t)idx * 8;
    float4 x0 = *(const float4*)s, x1 = *(const float4*)(s + 4);
    float vals[8] = {x0.x, x0.y, x0.z, x0.w, x1.x, x1.y, x1.z, x1.w};
    Pack8 h;
    #pragma unroll
    for (int j = 0; j < 8; j++) h.s[j] = __half_as_ushort(__float2half_rn(vals[j]));
    *(uint4*)(dst + (size_t)idx * 8) = h.v;
}

// B-split [hi|lo], row stride 2K (W2 only now)
__global__ void split3B_kernel(const float* __restrict__ src, unsigned short* __restrict__ dst,
                               int Kv /* K/8 */, int K) {
    int idx = blockIdx.x * blockDim.x + threadIdx.x;  // R*Kv
    int kv = idx % Kv, r = idx / Kv;
    const float* s = src + (size_t)r * K + kv * 8;
    float4 x0 = *(const float4*)s, x1 = *(const float4*)(s + 4);
    float vals[8] = {x0.x, x0.y, x0.z, x0.w, x1.x, x1.y, x1.z, x1.w};
    Pack8 hi, lo;
    #pragma unroll
    for (int j = 0; j < 8; j++) split_hi_lo(vals[j], hi.s[j], lo.s[j]);
    size_t e0 = (size_t)r * 2 * K + kv * 8;
    *(uint4*)(dst + e0)     = hi.v;
    *(uint4*)(dst + e0 + K) = lo.v;
}

__global__ void pre_A2_kernel(const float* __restrict__ w2) {
    int idx = blockIdx.x * blockDim.x + threadIdx.x;  // 512*512*4
    int q = idx & 3;
    int cf = idx >> 2;
    int f = cf & 511;
    int c = cf >> 9;
    int ip = q >> 1, jp = q & 1;
    const float* wb = w2 + (size_t)(c * 512 + f) * 9;
    float s = 0.f;
    #pragma unroll
    for (int i = 0; i < 2; i++)
        #pragma unroll
        for (int j = 0; j < 2; j++)
            s += wb[(ip - i + 1) * 3 + (jp - j + 1)];
    unsigned short hi, lo;
    split_hi_lo(0.25f * s, hi, lo);
    size_t e0 = (size_t)c * 4096 + f * 4 + q;
    g_A23[e0]        = hi;
    g_A23[e0 + 2048] = lo;
}

// conv B: W3[n=t*512+c][di*512+f], fp16, row stride 1536
__global__ void build_w3_kernel(const float* __restrict__ c1w) {
    int idx = blockIdx.x * blockDim.x + threadIdx.x;   // 1536*3*64
    int fg = idx & 63;
    int di = (idx >> 6) % 3;
    int n  = idx / 192;
    int t = n >> 9, c = n & 511;
    Pack8 hi;
    #pragma unroll
    for (int j = 0; j < 8; j++) {
        int f = fg * 8 + j;
        size_t base = ((size_t)(c * 512 + f) * 3 + di) * 3;
        float w;
        if (t == 0)      w = c1w[base] + c1w[base + 1] + c1w[base + 2];
        else if (t == 1) w = c1w[base];
        else             w = c1w[base + 2];
        hi.s[j] = __half_as_ushort(__float2half_rn(w));
    }
    *(uint4*)(g_W3 + (size_t)n * 1536 + di * 512 + fg * 8) = hi.v;
}

// conv A: pure fp16 gather, X16[r=(b,i)][di*512+f] = vaT16[b][i+di-1][f] (0 if OOB)
__global__ void build_x16_kernel() {
    int idx = blockIdx.x * blockDim.x + threadIdx.x;   // 8192*3*64
    int fg = idx & 63;
    int di = (idx >> 6) % 3;
    int r  = idx / 192;
    int b = r >> 3, i = r & 7;
    int src = i + di - 1;
    uint4 v = make_uint4(0, 0, 0, 0);
    if (src >= 0 && src < 8)
        v = *(const uint4*)(g_vaT16 + ((size_t)(b * 8 + src) * 512) + fg * 8);
    *(uint4*)(g_X16 + (size_t)r * 1536 + di * 512 + fg * 8) = v;
}

// ---------------- unified HMMA GEMM ----------------
// TERMS==3: stored [hi|lo] stride 2Ks/3; A logical [hi|lo|hi], B [hi|hi|lo].
// TERMS==2: stored stride Ks; A logical [hi|lo] (kA=k), B [hi|hi] (kB remap).
// TERMS==1: plain GEMM, stride Ks, kA=kB=k.
// MODE 0: fp16 Y store (conv)       MODE 1: relu(acc+bias) float (G3->out)
// MODE 2: h3 exact-split store (G1) MODE 3: vaT16 fp16 epilogue (G2)
template <int TM, int MODE, int TERMS>
__global__ void __launch_bounds__((TM == 256) ? 512 : 256, (TM == 256) ? 1 : 2)
hmma_kernel(const unsigned short* __restrict__ A, const unsigned short* __restrict__ Bm,
            const float* __restrict__ bias, float* __restrict__ outF,
            unsigned short* __restrict__ outH, const float* __restrict__ vx,
            int Ks, int ldc, size_t batchA, size_t batchB, int batchBias)
{
    constexpr int THREADS = (TM == 256) ? 512 : 256;
    constexpr int ROWS = TM + 128;
    constexpr int CH = ROWS * 4 / THREADS;
    constexpr int WMC = TM / 64;
    constexpr int ABUF = TM * LDK;
    constexpr int BBUF = 128 * LDK;

    extern __shared__ __align__(16) unsigned short smem[];
    unsigned short* sA = smem;                 // [2][ABUF]
    unsigned short* sB = smem + 2 * ABUF;      // [2][BBUF]

    const int tid = threadIdx.x;
    const int wid = tid >> 5, lane = tid & 31;
    const int m0 = blockIdx.y * TM;
    const int n0 = blockIdx.x * 128;
    const int z  = blockIdx.z;
    const int wm = (wid % WMC) * 64;
    const int wn = (wid / WMC) * 32;

    const int SK = (TERMS == 3) ? (2 * Ks) / 3 : Ks;   // stored row stride
    const int NIT = Ks / 32;
    const int nb = (TERMS == 3) ? NIT / 3 : NIT / 2;

    A  += (size_t)z * batchA;
    Bm += (size_t)z * batchB;
    if (MODE >= 1) bias += (size_t)z * batchBias;

    // staging maps (cp.async)
    const unsigned short* gp[CH];
    uint32_t sdA[CH];
    bool isA_[CH];
    #pragma unroll
    for (int t = 0; t < CH; t++) {
        int id = tid + t * THREADS;
        int r = id >> 2, q = id & 3;
        if (r < TM) {
            gp[t] = A + (size_t)(m0 + r) * SK + q * 8;
            sdA[t] = smem_u32(sA + r * LDK + q * 8);
            isA_[t] = true;
        } else {
            gp[t] = Bm + (size_t)(n0 + r - TM) * SK + q * 8;
            sdA[t] = smem_u32(sB + (r - TM) * LDK + q * 8);
            isA_[t] = false;
        }
    }

    float acc[4][4][4];
    #pragma unroll
    for (int i = 0; i < 4; i++)
        #pragma unroll
        for (int j = 0; j < 4; j++)
            #pragma unroll
            for (int q = 0; q < 4; q++) acc[i][j][q] = 0.f;

    const uint32_t sA_base = smem_u32(sA);
    const uint32_t sB_base = smem_u32(sB);
    const int aRow = wm + (lane & 15);
    const int aKof = (lane >> 4) * 8;
    const int bRow = wn + ((lane & 7) | ((lane >> 4) << 3));
    const int bKof = ((lane >> 3) & 1) * 8;

    // stage logical chunk k into buffer buf (uniform for all threads)
    auto stage = [&](int k, int buf) {
        int kA, kB;
        if (TERMS == 3)      { kA = (k < 2 * nb) ? k : k - 2 * nb; kB = (k < nb) ? k : k - nb; }
        else if (TERMS == 2) { kA = k;                             kB = (k < nb) ? k : k - nb; }
        else                 { kA = k;                             kB = k; }
        #pragma unroll
        for (int t = 0; t < CH; t++) {
            const unsigned short* src = gp[t] + (size_t)(isA_[t] ? kA : kB) * 32;
            uint32_t dst = sdA[t] + (uint32_t)buf * (isA_[t] ? ABUF : BBUF) * 2;
            cp_async16(dst, src);
        }
        CP_COMMIT();
    };

    stage(0, 0);
    CP_WAIT0();
    __syncthreads();

    for (int it = 0; it < NIT; it++) {
        const int cur = it & 1;
        const bool more = (it + 1) < NIT;
        if (more) stage(it + 1, cur ^ 1);

        const uint32_t aBuf = sA_base + cur * (ABUF * 2);
        const uint32_t bBuf = sB_base + cur * (BBUF * 2);
        #pragma unroll
        for (int ks = 0; ks < 32; ks += 16) {
            uint32_t af[4][4], bf[4][2];
            #pragma unroll
            for (int mt = 0; mt < 4; mt++)
                ldmatrix_x4(af[mt][0], af[mt][1], af[mt][2], af[mt][3],
                            aBuf + (uint32_t)(((aRow + mt * 16) * LDK + ks + aKof) * 2));
            #pragma unroll
            for (int np = 0; np < 2; np++)
                ldmatrix_x4(bf[np * 2][0], bf[np * 2][1], bf[np * 2 + 1][0], bf[np * 2 + 1][1],
                            bBuf + (uint32_t)(((bRow + np * 16) * LDK + ks + bKof) * 2));
            #pragma unroll
            for (int mt = 0; mt < 4; mt++)
                #pragma unroll
                for (int nt = 0; nt < 4; nt++)
                    mma_16816(acc[mt][nt], af[mt], bf[nt]);
        }
        if (more) CP_WAIT0();
        __syncthreads();
    }

    // epilogue
    const int erow = lane >> 2;
    const int ecol = (lane & 3) * 2;
    #pragma unroll
    for (int mt = 0; mt < 4; mt++) {
        #pragma unroll
        for (int nt = 0; nt < 4; nt++) {
            const int r0 = m0 + wm + mt * 16 + erow;
            const int c  = n0 + wn + nt * 8 + ecol;
            const float* v = acc[mt][nt];
            if (MODE == 0) {
                // fp16 Y store
                #pragma unroll
                for (int hr = 0; hr < 2; hr++) {
                    uint32_t pk = (uint32_t)__half_as_ushort(__float2half_rn(v[hr * 2]))
                                | ((uint32_t)__half_as_ushort(__float2half_rn(v[hr * 2 + 1])) << 16);
                    *(uint32_t*)&outH[(size_t)(r0 + hr * 8) * ldc + c] = pk;
                }
            } else if (MODE == 1) {
                float b0 = bias[c], b1 = bias[c + 1];
                *(float2*)&outF[(size_t)r0 * ldc + c] =
                    make_float2(fmaxf(v[0] + b0, 0.f), fmaxf(v[1] + b1, 0.f));
                *(float2*)&outF[(size_t)(r0 + 8) * ldc + c] =
                    make_float2(fmaxf(v[2] + b0, 0.f), fmaxf(v[3] + b1, 0.f));
            } else if (MODE == 2) {
                float b0 = bias[c], b1 = bias[c + 1];
                int zz = c >> 9, f = c & 511;
                #pragma unroll
                for (int hr = 0; hr < 2; hr++) {
                    float y0 = fmaxf(v[hr * 2] + b0, 0.f);
                    float y1 = fmaxf(v[hr * 2 + 1] + b1, 0.f);
                    unsigned short h0, l0, h1, l1;
                    split_hi_lo(y0, h0, l0);
                    split_hi_lo(y1, h1, l1);
                    uint32_t hip = (uint32_t)h0 | ((uint32_t)h1 << 16);
                    uint32_t lop = (uint32_t)l0 | ((uint32_t)l1 << 16);
                    size_t base = ((size_t)zz * 1024 + (r0 + hr * 8)) * 1024 + f;
                    *(uint32_t*)&outH[base]       = hip;
                    *(uint32_t*)&outH[base + 512] = lop;
                }
            } else {  // MODE 3: fp16 vaT epilogue
                float b0 = bias[c], b1 = bias[c + 1];
                #pragma unroll
                for (int hr = 0; hr < 2; hr++) {
                    int r = r0 + hr * 8;
                    float s0 = vx[(size_t)r * 512 + c];
                    float s1 = vx[(size_t)r * 512 + c + 1];
                    float y0 = s0 * fmaxf(v[hr * 2] + b0, 0.f);
                    float y1 = s1 * fmaxf(v[hr * 2 + 1] + b1, 0.f);
                    uint32_t pk = (uint32_t)__half_as_ushort(__float2half_rn(y0))
                                | ((uint32_t)__half_as_ushort(__float2half_rn(y1)) << 16);
                    *(uint32_t*)&outH[((size_t)r * 8 + z) * 512 + c] = pk;
                }
            }
        }
    }
}

// ---------------- pool: Y16 -> p3 (exact split) ----------------
__global__ void pool_split_kernel(const unsigned short* __restrict__ Y,
                                  const float* __restrict__ c1b) {
    int idx = blockIdx.x * blockDim.x + threadIdx.x;   // 1024*512
    int c = idx & 511, b = idx >> 9;
    float bias = c1b[c];
    float m00 = -1e30f, m01 = -1e30f, m10 = -1e30f, m11 = -1e30f;
    #pragma unroll
    for (int i = 0; i < 8; i++) {
        size_t base = (size_t)(b * 8 + i) * 1536;
        float yM = __half2float(__ushort_as_half(Y[base + c]));
        float yB = __half2float(__ushort_as_half(Y[base + 512 + c]));
        float yC = __half2float(__ushort_as_half(Y[base + 1024 + c]));
        float vL = fmaxf(yM - yB, yM);
        float vR = fmaxf(yM - yC, yM);
        if (i < 4) { m00 = fmaxf(m00, vL); m01 = fmaxf(m01, vR); }
        else       { m10 = fmaxf(m10, vL); m11 = fmaxf(m11, vR); }
    }
    float p[4] = {m00 + bias, m01 + bias, m10 + bias, m11 + bias};
    ushort4 hi, lo;
    split_hi_lo(p[0], hi.x, lo.x);
    split_hi_lo(p[1], hi.y, lo.y);
    split_hi_lo(p[2], hi.z, lo.z);
    split_hi_lo(p[3], hi.w, lo.w);
    size_t e0 = (size_t)b * 4096 + c * 4;
    *(ushort4*)(g_p3 + e0)        = hi;
    *(ushort4*)(g_p3 + e0 + 2048) = lo;
}

// ---------------- launch ----------------
extern "C" void kernel_launch(void* const* d_in, const int* in_sizes, int n_in,
                              void* d_out, int out_size) {
    (void)in_sizes; (void)n_in; (void)out_size;
    const float* vx  = (const float*)d_in[0];
    const float* ax  = (const float*)d_in[1];
    const float* W1  = (const float*)d_in[2];
    const float* b1  = (const float*)d_in[3];
    const float* W2  = (const float*)d_in[4];
    const float* b2  = (const float*)d_in[5];
    const float* c1w = (const float*)d_in[6];
    const float* c1b = (const float*)d_in[7];
    const float* c2w = (const float*)d_in[8];
    const float* c2b = (const float*)d_in[9];
    float* out = (float*)d_out;

    void *p_xcat16, *p_W16, *p_h3, *p_W23, *p_vaT16, *p_X16, *p_W3, *p_Y16, *p_p3, *p_A23;
    cudaGetSymbolAddress(&p_xcat16, g_xcat16);
    cudaGetSymbolAddress(&p_W16,    g_W16);
    cudaGetSymbolAddress(&p_h3,     g_h3);
    cudaGetSymbolAddress(&p_W23,    g_W23);
    cudaGetSymbolAddress(&p_vaT16,  g_vaT16);
    cudaGetSymbolAddress(&p_X16,    g_X16);
    cudaGetSymbolAddress(&p_W3,     g_W3);
    cudaGetSymbolAddress(&p_Y16,    g_Y16);
    cudaGetSymbolAddress(&p_p3,     g_p3);
    cudaGetSymbolAddress(&p_A23,    g_A23);

    const int SM256 = (2 * 256 + 2 * 128) * LDK * 2;  // 61440
    const int SM128 = (2 * 128 + 2 * 128) * LDK * 2;  // 40960
    cudaFuncSetAttribute((const void*)hmma_kernel<256, 2, 1>, cudaFuncAttributeMaxDynamicSharedMemorySize, SM256);
    cudaFuncSetAttribute((const void*)hmma_kernel<256, 3, 2>, cudaFuncAttributeMaxDynamicSharedMemorySize, SM256);
    cudaFuncSetAttribute((const void*)hmma_kernel<256, 0, 1>, cudaFuncAttributeMaxDynamicSharedMemorySize, SM256);
    cudaFuncSetAttribute((const void*)hmma_kernel<128, 1, 2>, cudaFuncAttributeMaxDynamicSharedMemorySize, SM128);

    // operand builders
    concat16_kernel<<<512, 256>>>(vx, ax);                                  // xcat16
    build16_kernel<<<2048, 256>>>(W1, (unsigned short*)p_W16, 4096 * 128);  // W1 fp16
    split3B_kernel<<<1024, 256>>>(W2, (unsigned short*)p_W23, 64, 512);     // W2 split
    pre_A2_kernel<<<4096, 256>>>(c2w);                                      // A2 split
    build_w3_kernel<<<1152, 256>>>(c1w);                                    // W3 fp16

    // GEMM1 (1-term): h3 = exact_split(relu(xcat16*W16^T + b1)); K=1024
    hmma_kernel<256, 2, 1><<<dim3(32, 4), 512, SM256>>>(
        (const unsigned short*)p_xcat16, (const unsigned short*)p_W16, b1,
        nullptr, (unsigned short*)p_h3, nullptr, 1024, 0, 0, 0, 0);

    // GEMM2 (2-term, batch z): vaT16 = fp16(vx*relu(h_z*W2h_z^T + b2_z)); K=1024
    hmma_kernel<256, 3, 2><<<dim3(4, 4, 8), 512, SM256>>>(
        (const unsigned short*)p_h3, (const unsigned short*)p_W23, b2,
        nullptr, (unsigned short*)p_vaT16, vx, 1024, 0,
        (size_t)1024 * 1024, (size_t)512 * 1024, 512);

    // conv A gather, then conv GEMM (1-term): Y16 = X16*W3^T; K=1536
    build_x16_kernel<<<6144, 256>>>();
    hmma_kernel<256, 0, 1><<<dim3(12, 32), 512, SM256>>>(
        (const unsigned short*)p_X16, (const unsigned short*)p_W3, nullptr,
        nullptr, (unsigned short*)p_Y16, nullptr, 1536, 1536, 0, 0, 0);

    // pool -> p3 (exact split)
    pool_split_kernel<<<2048, 256>>>((const unsigned short*)p_Y16, c1b);

    // GEMM3 (2-term): out = relu(p*A2h^T + c2b); K=4096
    hmma_kernel<128, 1, 2><<<dim3(4, 8), 256, SM128>>>(
        (const unsigned short*)p_p3, (const unsigned short*)p_A23, c2b,
        out, nullptr, nullptr, 4096, 512, 0, 0, 0);
}

// round 12
// speedup vs baseline: 2.2881x; 1.2541x over previous
#include <cuda_runtime.h>
#include <cuda_fp16.h>
#include <cstdint>
#include <cstddef>

// B=1024, F=512, N=8 — HMMA fp16 (fp32 accum).
// G1: 1-term (fp16 x × fp16 W1) -> plain fp16 h.
// G2: 1-term (fp16 h × fp16 W2) -> fp16 vaT.
// conv: 1-term, materialized fp16 gather operand, fp16 Y.
// G3: 2-term (exact-p split × A2hi), split-K=4 into fp32 partials + reduce.
// Error budget ~4.7e-4 (quadrature of ~6 fp16-quant sources).

#define LDK 40   // smem row stride in halves (80B, conflict-free ldmatrix)

// ---------------- static scratch ----------------
__device__ unsigned short g_xcat16[(size_t)1024 * 1024];  // fp16 [vx|ax]
__device__ unsigned short g_W16[(size_t)4096 * 1024];     // fp16 W1
__device__ unsigned short g_h16[(size_t)8 * 1024 * 512];  // fp16 h, [z][b][f]
__device__ unsigned short g_W216[(size_t)4096 * 512];     // fp16 W2
__device__ unsigned short g_vaT16[(size_t)1024 * 8 * 512];// fp16 va, [b][i][f]
__device__ unsigned short g_X16[(size_t)8192 * 1536];     // conv A, fp16 (di-shifted)
__device__ unsigned short g_W3[(size_t)1536 * 1536];      // conv B, fp16
__device__ unsigned short g_Y16[(size_t)8192 * 1536];     // conv out, fp16
__device__ unsigned short g_p3[(size_t)1024 * 4096];      // pooled exact split [hi|lo]
__device__ unsigned short g_A23[(size_t)512 * 4096];      // conv2-collapsed split [hi|lo]
__device__ float g_part[(size_t)4 * 1024 * 512];          // G3 split-K partials

// ---------------- helpers ----------------
union Pack8 { unsigned short s[8]; uint4 v; };
__device__ __forceinline__ void split_hi_lo(float x, unsigned short& hi, unsigned short& lo) {
    __half h = __float2half_rn(x);
    float hf = __half2float(h);
    __half l = __float2half_rn(x - hf);
    hi = __half_as_ushort(h);
    lo = __half_as_ushort(l);
}
__device__ __forceinline__ uint32_t smem_u32(const void* p) {
    uint32_t a;
    asm("{ .reg .u64 t; cvta.to.shared.u64 t, %1; cvt.u32.u64 %0, t; }" : "=r"(a) : "l"(p));
    return a;
}
__device__ __forceinline__ void ldmatrix_x4(uint32_t& r0, uint32_t& r1, uint32_t& r2, uint32_t& r3,
                                            uint32_t addr) {
    asm volatile("ldmatrix.sync.aligned.m8n8.x4.shared.b16 {%0,%1,%2,%3}, [%4];"
                 : "=r"(r0), "=r"(r1), "=r"(r2), "=r"(r3) : "r"(addr));
}
__device__ __forceinline__ void mma_16816(float* c, const uint32_t* a, const uint32_t* b) {
    asm volatile("mma.sync.aligned.m16n8k16.row.col.f32.f16.f16.f32 "
                 "{%0,%1,%2,%3}, {%4,%5,%6,%7}, {%8,%9}, {%0,%1,%2,%3};"
                 : "+f"(c[0]), "+f"(c[1]), "+f"(c[2]), "+f"(c[3])
                 : "r"(a[0]), "r"(a[1]), "r"(a[2]), "r"(a[3]), "r"(b[0]), "r"(b[1]));
}
__device__ __forceinline__ void cp_async16(uint32_t dst, const void* src) {
    asm volatile("cp.async.cg.shared.global [%0], [%1], 16;" :: "r"(dst), "l"(src));
}
#define CP_COMMIT() asm volatile("cp.async.commit_group;" ::: "memory")
#define CP_WAIT0()  asm volatile("cp.async.wait_group 0;" ::: "memory")

// ---------------- operand builders ----------------
__global__ void concat16_kernel(const float* __restrict__ vx, const float* __restrict__ ax) {
    int idx = blockIdx.x * blockDim.x + threadIdx.x;  // 1024*128
    int kv = idx & 127, b = idx >> 7;
    const float* src = (kv < 64) ? (vx + (size_t)b * 512 + kv * 8)
                                 : (ax + (size_t)b * 512 + (kv - 64) * 8);
    float4 x0 = *(const float4*)src, x1 = *(const float4*)(src + 4);
    float vals[8] = {x0.x, x0.y, x0.z, x0.w, x1.x, x1.y, x1.z, x1.w};
    Pack8 h;
    #pragma unroll
    for (int j = 0; j < 8; j++) h.s[j] = __half_as_ushort(__float2half_rn(vals[j]));
    *(uint4*)(g_xcat16 + (size_t)b * 1024 + kv * 8) = h.v;
}

// plain float -> fp16, vectorized (n8 = elements/8)
__global__ void build16_kernel(const float* __restrict__ src, unsigned short* __restrict__ dst,
                               int n8) {
    int idx = blockIdx.x * blockDim.x + threadIdx.x;
    if (idx >= n8) return;
    const float* s = src + (size_t)idx * 8;
    float4 x0 = *(const float4*)s, x1 = *(const float4*)(s + 4);
    float vals[8] = {x0.x, x0.y, x0.z, x0.w, x1.x, x1.y, x1.z, x1.w};
    Pack8 h;
    #pragma unroll
    for (int j = 0; j < 8; j++) h.s[j] = __half_as_ushort(__float2half_rn(vals[j]));
    *(uint4*)(dst + (size_t)idx * 8) = h.v;
}

__global__ void pre_A2_kernel(const float* __restrict__ w2) {
    int idx = blockIdx.x * blockDim.x + threadIdx.x;  // 512*512*4
    int q = idx & 3;
    int cf = idx >> 2;
    int f = cf & 511;
    int c = cf >> 9;
    int ip = q >> 1, jp = q & 1;
    const float* wb = w2 + (size_t)(c * 512 + f) * 9;
    float s = 0.f;
    #pragma unroll
    for (int i = 0; i < 2; i++)
        #pragma unroll
        for (int j = 0; j < 2; j++)
            s += wb[(ip - i + 1) * 3 + (jp - j + 1)];
    unsigned short hi, lo;
    split_hi_lo(0.25f * s, hi, lo);
    size_t e0 = (size_t)c * 4096 + f * 4 + q;
    g_A23[e0]        = hi;
    g_A23[e0 + 2048] = lo;
}

// conv B: W3[n=t*512+c][di*512+f], fp16, row stride 1536
__global__ void build_w3_kernel(const float* __restrict__ c1w) {
    int idx = blockIdx.x * blockDim.x + threadIdx.x;   // 1536*3*64
    int fg = idx & 63;
    int di = (idx >> 6) % 3;
    int n  = idx / 192;
    int t = n >> 9, c = n & 511;
    Pack8 hi;
    #pragma unroll
    for (int j = 0; j < 8; j++) {
        int f = fg * 8 + j;
        size_t base = ((size_t)(c * 512 + f) * 3 + di) * 3;
        float w;
        if (t == 0)      w = c1w[base] + c1w[base + 1] + c1w[base + 2];
        else if (t == 1) w = c1w[base];
        else             w = c1w[base + 2];
        hi.s[j] = __half_as_ushort(__float2half_rn(w));
    }
    *(uint4*)(g_W3 + (size_t)n * 1536 + di * 512 + fg * 8) = hi.v;
}

// conv A: pure fp16 gather, X16[r=(b,i)][di*512+f] = vaT16[b][i+di-1][f] (0 if OOB)
__global__ void build_x16_kernel() {
    int idx = blockIdx.x * blockDim.x + threadIdx.x;   // 8192*3*64
    int fg = idx & 63;
    int di = (idx >> 6) % 3;
    int r  = idx / 192;
    int b = r >> 3, i = r & 7;
    int src = i + di - 1;
    uint4 v = make_uint4(0, 0, 0, 0);
    if (src >= 0 && src < 8)
        v = *(const uint4*)(g_vaT16 + ((size_t)(b * 8 + src) * 512) + fg * 8);
    *(uint4*)(g_X16 + (size_t)r * 1536 + di * 512 + fg * 8) = v;
}

// ---------------- unified HMMA GEMM ----------------
// TERMS==2: stored stride SKp; A logical [hi|lo] (kA=kg), B [hi|hi] (kB remap, nbP).
// TERMS==1: plain GEMM, kA=kB=kg.
// MODE 0: fp16 store (conv Y)       MODE 2: fp16 h store [z][b][f] (G1)
// MODE 3: vaT16 fp16 epilogue (G2)  MODE 4: raw float partial store, z-offset (G3 split-K)
template <int TM, int MODE, int TERMS>
__global__ void __launch_bounds__((TM == 256) ? 512 : 256, (TM == 256) ? 1 : 2)
hmma_kernel(const unsigned short* __restrict__ A, const unsigned short* __restrict__ Bm,
            const float* __restrict__ bias, float* __restrict__ outF,
            unsigned short* __restrict__ outH, const float* __restrict__ vx,
            int Ks, int SKp, int nbP, int ldc,
            size_t batchA, size_t batchB, int batchBias)
{
    constexpr int THREADS = (TM == 256) ? 512 : 256;
    constexpr int ROWS = TM + 128;
    constexpr int CH = ROWS * 4 / THREADS;
    constexpr int WMC = TM / 64;
    constexpr int ABUF = TM * LDK;
    constexpr int BBUF = 128 * LDK;

    extern __shared__ __align__(16) unsigned short smem[];
    unsigned short* sA = smem;                 // [2][ABUF]
    unsigned short* sB = smem + 2 * ABUF;      // [2][BBUF]

    const int tid = threadIdx.x;
    const int wid = tid >> 5, lane = tid & 31;
    const int m0 = blockIdx.y * TM;
    const int n0 = blockIdx.x * 128;
    const int z  = blockIdx.z;
    const int wm = (wid % WMC) * 64;
    const int wn = (wid / WMC) * 32;

    const int NIT = Ks / 32;
    const int koff = (MODE == 4) ? z * NIT : 0;

    A  += (size_t)z * batchA;
    Bm += (size_t)z * batchB;
    if (MODE == 2 || MODE == 3) bias += (size_t)z * batchBias;

    // staging maps (cp.async)
    const unsigned short* gp[CH];
    uint32_t sdA[CH];
    bool isA_[CH];
    #pragma unroll
    for (int t = 0; t < CH; t++) {
        int id = tid + t * THREADS;
        int r = id >> 2, q = id & 3;
        if (r < TM) {
            gp[t] = A + (size_t)(m0 + r) * SKp + q * 8;
            sdA[t] = smem_u32(sA + r * LDK + q * 8);
            isA_[t] = true;
        } else {
            gp[t] = Bm + (size_t)(n0 + r - TM) * SKp + q * 8;
            sdA[t] = smem_u32(sB + (r - TM) * LDK + q * 8);
            isA_[t] = false;
        }
    }

    float acc[4][4][4];
    #pragma unroll
    for (int i = 0; i < 4; i++)
        #pragma unroll
        for (int j = 0; j < 4; j++)
            #pragma unroll
            for (int q = 0; q < 4; q++) acc[i][j][q] = 0.f;

    const uint32_t sA_base = smem_u32(sA);
    const uint32_t sB_base = smem_u32(sB);
    const int aRow = wm + (lane & 15);
    const int aKof = (lane >> 4) * 8;
    const int bRow = wn + ((lane & 7) | ((lane >> 4) << 3));
    const int bKof = ((lane >> 3) & 1) * 8;

    // stage local chunk k (global kg = k + koff) into buffer buf
    auto stage = [&](int k, int buf) {
        int kg = k + koff;
        int kA = kg;
        int kB = (TERMS == 2) ? ((kg < nbP) ? kg : kg - nbP) : kg;
        #pragma unroll
        for (int t = 0; t < CH; t++) {
            const unsigned short* src = gp[t] + (size_t)(isA_[t] ? kA : kB) * 32;
            uint32_t dst = sdA[t] + (uint32_t)buf * (isA_[t] ? ABUF : BBUF) * 2;
            cp_async16(dst, src);
        }
        CP_COMMIT();
    };

    stage(0, 0);
    CP_WAIT0();
    __syncthreads();

    for (int it = 0; it < NIT; it++) {
        const int cur = it & 1;
        const bool more = (it + 1) < NIT;
        if (more) stage(it + 1, cur ^ 1);

        const uint32_t aBuf = sA_base + cur * (ABUF * 2);
        const uint32_t bBuf = sB_base + cur * (BBUF * 2);
        #pragma unroll
        for (int ks = 0; ks < 32; ks += 16) {
            uint32_t af[4][4], bf[4][2];
            #pragma unroll
            for (int mt = 0; mt < 4; mt++)
                ldmatrix_x4(af[mt][0], af[mt][1], af[mt][2], af[mt][3],
                            aBuf + (uint32_t)(((aRow + mt * 16) * LDK + ks + aKof) * 2));
            #pragma unroll
            for (int np = 0; np < 2; np++)
                ldmatrix_x4(bf[np * 2][0], bf[np * 2][1], bf[np * 2 + 1][0], bf[np * 2 + 1][1],
                            bBuf + (uint32_t)(((bRow + np * 16) * LDK + ks + bKof) * 2));
            #pragma unroll
            for (int mt = 0; mt < 4; mt++)
                #pragma unroll
                for (int nt = 0; nt < 4; nt++)
                    mma_16816(acc[mt][nt], af[mt], bf[nt]);
        }
        if (more) CP_WAIT0();
        __syncthreads();
    }

    // epilogue
    const int erow = lane >> 2;
    const int ecol = (lane & 3) * 2;
    #pragma unroll
    for (int mt = 0; mt < 4; mt++) {
        #pragma unroll
        for (int nt = 0; nt < 4; nt++) {
            const int r0 = m0 + wm + mt * 16 + erow;
            const int c  = n0 + wn + nt * 8 + ecol;
            const float* v = acc[mt][nt];
            if (MODE == 0) {
                #pragma unroll
                for (int hr = 0; hr < 2; hr++) {
                    uint32_t pk = (uint32_t)__half_as_ushort(__float2half_rn(v[hr * 2]))
                                | ((uint32_t)__half_as_ushort(__float2half_rn(v[hr * 2 + 1])) << 16);
                    *(uint32_t*)&outH[(size_t)(r0 + hr * 8) * ldc + c] = pk;
                }
            } else if (MODE == 2) {
                float b0 = bias[c], b1 = bias[c + 1];
                int zz = c >> 9, f = c & 511;
                #pragma unroll
                for (int hr = 0; hr < 2; hr++) {
                    float y0 = fmaxf(v[hr * 2] + b0, 0.f);
                    float y1 = fmaxf(v[hr * 2 + 1] + b1, 0.f);
                    uint32_t pk = (uint32_t)__half_as_ushort(__float2half_rn(y0))
                                | ((uint32_t)__half_as_ushort(__float2half_rn(y1)) << 16);
                    *(uint32_t*)&outH[((size_t)zz * 1024 + (r0 + hr * 8)) * 512 + f] = pk;
                }
            } else if (MODE == 3) {
                float b0 = bias[c], b1 = bias[c + 1];
                #pragma unroll
                for (int hr = 0; hr < 2; hr++) {
                    int r = r0 + hr * 8;
                    float s0 = vx[(size_t)r * 512 + c];
                    float s1 = vx[(size_t)r * 512 + c + 1];
                    float y0 = s0 * fmaxf(v[hr * 2] + b0, 0.f);
                    float y1 = s1 * fmaxf(v[hr * 2 + 1] + b1, 0.f);
                    uint32_t pk = (uint32_t)__half_as_ushort(__float2half_rn(y0))
                                | ((uint32_t)__half_as_ushort(__float2half_rn(y1)) << 16);
                    *(uint32_t*)&outH[((size_t)r * 8 + z) * 512 + c] = pk;
                }
            } else {  // MODE 4: raw float partial, z-offset
                float* o = outF + (size_t)z * batchBias;
                *(float2*)&o[(size_t)r0 * ldc + c] = make_float2(v[0], v[1]);
                *(float2*)&o[(size_t)(r0 + 8) * ldc + c] = make_float2(v[2], v[3]);
            }
        }
    }
}

// ---------------- pool: Y16 -> p3 (exact split) ----------------
__global__ void pool_split_kernel(const unsigned short* __restrict__ Y,
                                  const float* __restrict__ c1b) {
    int idx = blockIdx.x * blockDim.x + threadIdx.x;   // 1024*512
    int c = idx & 511, b = idx >> 9;
    float bias = c1b[c];
    float m00 = -1e30f, m01 = -1e30f, m10 = -1e30f, m11 = -1e30f;
    #pragma unroll
    for (int i = 0; i < 8; i++) {
        size_t base = (size_t)(b * 8 + i) * 1536;
        float yM = __half2float(__ushort_as_half(Y[base + c]));
        float yB = __half2float(__ushort_as_half(Y[base + 512 + c]));
        float yC = __half2float(__ushort_as_half(Y[base + 1024 + c]));
        float vL = fmaxf(yM - yB, yM);
        float vR = fmaxf(yM - yC, yM);
        if (i < 4) { m00 = fmaxf(m00, vL); m01 = fmaxf(m01, vR); }
        else       { m10 = fmaxf(m10, vL); m11 = fmaxf(m11, vR); }
    }
    float p[4] = {m00 + bias, m01 + bias, m10 + bias, m11 + bias};
    ushort4 hi, lo;
    split_hi_lo(p[0], hi.x, lo.x);
    split_hi_lo(p[1], hi.y, lo.y);
    split_hi_lo(p[2], hi.z, lo.z);
    split_hi_lo(p[3], hi.w, lo.w);
    size_t e0 = (size_t)b * 4096 + c * 4;
    *(ushort4*)(g_p3 + e0)        = hi;
    *(ushort4*)(g_p3 + e0 + 2048) = lo;
}

// ---------------- G3 reduce: sum 4 partials + bias, relu ----------------
__global__ void reduce_relu_kernel(const float* __restrict__ parts,
                                   const float* __restrict__ bias,
                                   float* __restrict__ out) {
    int idx = blockIdx.x * blockDim.x + threadIdx.x;   // 1024*512/4
    size_t e = (size_t)idx * 4;
    int c = (int)(e & 511);
    float4 a = *(const float4*)(parts + e);
    float4 b = *(const float4*)(parts + e + 524288);
    float4 d = *(const float4*)(parts + e + 2 * 524288);
    float4 f = *(const float4*)(parts + e + 3 * 524288);
    float4 bi = *(const float4*)(bias + c);
    float4 r;
    r.x = fmaxf(a.x + b.x + d.x + f.x + bi.x, 0.f);
    r.y = fmaxf(a.y + b.y + d.y + f.y + bi.y, 0.f);
    r.z = fmaxf(a.z + b.z + d.z + f.z + bi.z, 0.f);
    r.w = fmaxf(a.w + b.w + d.w + f.w + bi.w, 0.f);
    *(float4*)(out + e) = r;
}

// ---------------- launch ----------------
extern "C" void kernel_launch(void* const* d_in, const int* in_sizes, int n_in,
                              void* d_out, int out_size) {
    (void)in_sizes; (void)n_in; (void)out_size;
    const float* vx  = (const float*)d_in[0];
    const float* ax  = (const float*)d_in[1];
    const float* W1  = (const float*)d_in[2];
    const float* b1  = (const float*)d_in[3];
    const float* W2  = (const float*)d_in[4];
    const float* b2  = (const float*)d_in[5];
    const float* c1w = (const float*)d_in[6];
    const float* c1b = (const float*)d_in[7];
    const float* c2w = (const float*)d_in[8];
    const float* c2b = (const float*)d_in[9];
    float* out = (float*)d_out;

    void *p_xcat16, *p_W16, *p_h16, *p_W216, *p_vaT16, *p_X16, *p_W3, *p_Y16, *p_p3, *p_A23, *p_part;
    cudaGetSymbolAddress(&p_xcat16, g_xcat16);
    cudaGetSymbolAddress(&p_W16,    g_W16);
    cudaGetSymbolAddress(&p_h16,    g_h16);
    cudaGetSymbolAddress(&p_W216,   g_W216);
    cudaGetSymbolAddress(&p_vaT16,  g_vaT16);
    cudaGetSymbolAddress(&p_X16,    g_X16);
    cudaGetSymbolAddress(&p_W3,     g_W3);
    cudaGetSymbolAddress(&p_Y16,    g_Y16);
    cudaGetSymbolAddress(&p_p3,     g_p3);
    cudaGetSymbolAddress(&p_A23,    g_A23);
    cudaGetSymbolAddress(&p_part,   g_part);

    const int SM256 = (2 * 256 + 2 * 128) * LDK * 2;  // 61440
    const int SM128 = (2 * 128 + 2 * 128) * LDK * 2;  // 40960
    cudaFuncSetAttribute((const void*)hmma_kernel<256, 2, 1>, cudaFuncAttributeMaxDynamicSharedMemorySize, SM256);
    cudaFuncSetAttribute((const void*)hmma_kernel<256, 3, 1>, cudaFuncAttributeMaxDynamicSharedMemorySize, SM256);
    cudaFuncSetAttribute((const void*)hmma_kernel<256, 0, 1>, cudaFuncAttributeMaxDynamicSharedMemorySize, SM256);
    cudaFuncSetAttribute((const void*)hmma_kernel<128, 4, 2>, cudaFuncAttributeMaxDynamicSharedMemorySize, SM128);

    // operand builders
    concat16_kernel<<<512, 256>>>(vx, ax);                                  // xcat16
    build16_kernel<<<2048, 256>>>(W1, (unsigned short*)p_W16, 4096 * 128);  // W1 fp16
    build16_kernel<<<1024, 256>>>(W2, (unsigned short*)p_W216, 4096 * 64);  // W2 fp16
    pre_A2_kernel<<<4096, 256>>>(c2w);                                      // A2 split
    build_w3_kernel<<<1152, 256>>>(c1w);                                    // W3 fp16

    // GEMM1 (1-term): h16 = fp16(relu(xcat16*W16^T + b1)); K=1024
    hmma_kernel<256, 2, 1><<<dim3(32, 4), 512, SM256>>>(
        (const unsigned short*)p_xcat16, (const unsigned short*)p_W16, b1,
        nullptr, (unsigned short*)p_h16, nullptr,
        1024, 1024, 0, 0, 0, 0, 0);

    // GEMM2 (1-term, batch z): vaT16 = fp16(vx*relu(h16_z*W216_z^T + b2_z)); K=512
    hmma_kernel<256, 3, 1><<<dim3(4, 4, 8), 512, SM256>>>(
        (const unsigned short*)p_h16, (const unsigned short*)p_W216, b2,
        nullptr, (unsigned short*)p_vaT16, vx,
        512, 512, 0, 0, (size_t)1024 * 512, (size_t)512 * 512, 512);

    // conv A gather, then conv GEMM (1-term): Y16 = X16*W3^T; K=1536
    build_x16_kernel<<<6144, 256>>>();
    hmma_kernel<256, 0, 1><<<dim3(12, 32), 512, SM256>>>(
        (const unsigned short*)p_X16, (const unsigned short*)p_W3, nullptr,
        nullptr, (unsigned short*)p_Y16, nullptr,
        1536, 1536, 0, 1536, 0, 0, 0);

    // pool -> p3 (exact split)
    pool_split_kernel<<<2048, 256>>>((const unsigned short*)p_Y16, c1b);

    // GEMM3 (2-term, split-K=4): part_z = p*A2h^T over K-slice z; logical K=4096
    hmma_kernel<128, 4, 2><<<dim3(4, 8, 4), 256, SM128>>>(
        (const unsigned short*)p_p3, (const unsigned short*)p_A23, nullptr,
        (float*)p_part, nullptr, nullptr,
        1024, 4096, 64, 512, 0, 0, 1024 * 512);

    // reduce partials + bias + relu -> out
    reduce_relu_kernel<<<512, 256>>>((const float*)p_part, c2b, out);
}

// round 13
// speedup vs baseline: 2.3335x; 1.0198x over previous
#include <cuda_runtime.h>
#include <cuda_fp16.h>
#include <cstdint>
#include <cstddef>

// B=1024, F=512, N=8 — HMMA fp16 (fp32 accum).
// G1 (1-term, TM=128 occ2): h16 = fp16(relu(x*W1+b1))
// G2 (1-term, TM=128 occ2): epilogue scatter-writes the di-shifted conv operand
//   X16 directly (3 bounded stores per value) — no gather kernel, no vaT16.
// conv (1-term, TM=256): Y16 = X16*W3^T
// G3 (2-term split-K=4, TM=128 occ2) + reduce.

#define LDK 40   // smem row stride in halves (80B, conflict-free ldmatrix)

// ---------------- static scratch ----------------
__device__ unsigned short g_xcat16[(size_t)1024 * 1024];  // fp16 [vx|ax]
__device__ unsigned short g_W16[(size_t)4096 * 1024];     // fp16 W1
__device__ unsigned short g_h16[(size_t)8 * 1024 * 512];  // fp16 h, [z][b][f]
__device__ unsigned short g_W216[(size_t)4096 * 512];     // fp16 W2
__device__ unsigned short g_X16[(size_t)8192 * 1536];     // conv A (scatter-written;
                                                          // boundary blocks stay bss-zero)
__device__ unsigned short g_W3[(size_t)1536 * 1536];      // conv B, fp16
__device__ unsigned short g_Y16[(size_t)8192 * 1536];     // conv out, fp16
__device__ unsigned short g_p3[(size_t)1024 * 4096];      // pooled exact split [hi|lo]
__device__ unsigned short g_A23[(size_t)512 * 4096];      // conv2-collapsed split [hi|lo]
__device__ float g_part[(size_t)4 * 1024 * 512];          // G3 split-K partials

// ---------------- helpers ----------------
union Pack8 { unsigned short s[8]; uint4 v; };
__device__ __forceinline__ void split_hi_lo(float x, unsigned short& hi, unsigned short& lo) {
    __half h = __float2half_rn(x);
    float hf = __half2float(h);
    __half l = __float2half_rn(x - hf);
    hi = __half_as_ushort(h);
    lo = __half_as_ushort(l);
}
__device__ __forceinline__ uint32_t smem_u32(const void* p) {
    uint32_t a;
    asm("{ .reg .u64 t; cvta.to.shared.u64 t, %1; cvt.u32.u64 %0, t; }" : "=r"(a) : "l"(p));
    return a;
}
__device__ __forceinline__ void ldmatrix_x4(uint32_t& r0, uint32_t& r1, uint32_t& r2, uint32_t& r3,
                                            uint32_t addr) {
    asm volatile("ldmatrix.sync.aligned.m8n8.x4.shared.b16 {%0,%1,%2,%3}, [%4];"
                 : "=r"(r0), "=r"(r1), "=r"(r2), "=r"(r3) : "r"(addr));
}
__device__ __forceinline__ void mma_16816(float* c, const uint32_t* a, const uint32_t* b) {
    asm volatile("mma.sync.aligned.m16n8k16.row.col.f32.f16.f16.f32 "
                 "{%0,%1,%2,%3}, {%4,%5,%6,%7}, {%8,%9}, {%0,%1,%2,%3};"
                 : "+f"(c[0]), "+f"(c[1]), "+f"(c[2]), "+f"(c[3])
                 : "r"(a[0]), "r"(a[1]), "r"(a[2]), "r"(a[3]), "r"(b[0]), "r"(b[1]));
}
__device__ __forceinline__ void cp_async16(uint32_t dst, const void* src) {
    asm volatile("cp.async.cg.shared.global [%0], [%1], 16;" :: "r"(dst), "l"(src));
}
#define CP_COMMIT() asm volatile("cp.async.commit_group;" ::: "memory")
#define CP_WAIT0()  asm volatile("cp.async.wait_group 0;" ::: "memory")

// ---------------- operand builders ----------------
__global__ void concat16_kernel(const float* __restrict__ vx, const float* __restrict__ ax) {
    int idx = blockIdx.x * blockDim.x + threadIdx.x;  // 1024*128
    int kv = idx & 127, b = idx >> 7;
    const float* src = (kv < 64) ? (vx + (size_t)b * 512 + kv * 8)
                                 : (ax + (size_t)b * 512 + (kv - 64) * 8);
    float4 x0 = *(const float4*)src, x1 = *(const float4*)(src + 4);
    float vals[8] = {x0.x, x0.y, x0.z, x0.w, x1.x, x1.y, x1.z, x1.w};
    Pack8 h;
    #pragma unroll
    for (int j = 0; j < 8; j++) h.s[j] = __half_as_ushort(__float2half_rn(vals[j]));
    *(uint4*)(g_xcat16 + (size_t)b * 1024 + kv * 8) = h.v;
}

__global__ void build16_kernel(const float* __restrict__ src, unsigned short* __restrict__ dst,
                               int n8) {
    int idx = blockIdx.x * blockDim.x + threadIdx.x;
    if (idx >= n8) return;
    const float* s = src + (size_t)idx * 8;
    float4 x0 = *(const float4*)s, x1 = *(const float4*)(s + 4);
    float vals[8] = {x0.x, x0.y, x0.z, x0.w, x1.x, x1.y, x1.z, x1.w};
    Pack8 h;
    #pragma unroll
    for (int j = 0; j < 8; j++) h.s[j] = __half_as_ushort(__float2half_rn(vals[j]));
    *(uint4*)(dst + (size_t)idx * 8) = h.v;
}

__global__ void pre_A2_kernel(const float* __restrict__ w2) {
    int idx = blockIdx.x * blockDim.x + threadIdx.x;  // 512*512*4
    int q = idx & 3;
    int cf = idx >> 2;
    int f = cf & 511;
    int c = cf >> 9;
    int ip = q >> 1, jp = q & 1;
    const float* wb = w2 + (size_t)(c * 512 + f) * 9;
    float s = 0.f;
    #pragma unroll
    for (int i = 0; i < 2; i++)
        #pragma unroll
        for (int j = 0; j < 2; j++)
            s += wb[(ip - i + 1) * 3 + (jp - j + 1)];
    unsigned short hi, lo;
    split_hi_lo(0.25f * s, hi, lo);
    size_t e0 = (size_t)c * 4096 + f * 4 + q;
    g_A23[e0]        = hi;
    g_A23[e0 + 2048] = lo;
}

// conv B: W3[n=t*512+c][di*512+f], fp16, row stride 1536
__global__ void build_w3_kernel(const float* __restrict__ c1w) {
    int idx = blockIdx.x * blockDim.x + threadIdx.x;   // 1536*3*64
    int fg = idx & 63;
    int di = (idx >> 6) % 3;
    int n  = idx / 192;
    int t = n >> 9, c = n & 511;
    Pack8 hi;
    #pragma unroll
    for (int j = 0; j < 8; j++) {
        int f = fg * 8 + j;
        size_t base = ((size_t)(c * 512 + f) * 3 + di) * 3;
        float w;
        if (t == 0)      w = c1w[base] + c1w[base + 1] + c1w[base + 2];
        else if (t == 1) w = c1w[base];
        else             w = c1w[base + 2];
        hi.s[j] = __half_as_ushort(__float2half_rn(w));
    }
    *(uint4*)(g_W3 + (size_t)n * 1536 + di * 512 + fg * 8) = hi.v;
}

// ---------------- unified HMMA GEMM ----------------
// TERMS==2: A logical [hi|lo] (kA=kg), B [hi|hi] (kB remap via nbP).
// TERMS==1: plain GEMM, kA=kB=kg.
// MODE 0: fp16 store (conv Y)       MODE 2: fp16 h store [z][b][f] (G1)
// MODE 3: X16 scatter epilogue (G2) MODE 4: raw float partial store, z-offset (G3)
template <int TM, int MODE, int TERMS>
__global__ void __launch_bounds__((TM == 256) ? 512 : 256, (TM == 256) ? 1 : 2)
hmma_kernel(const unsigned short* __restrict__ A, const unsigned short* __restrict__ Bm,
            const float* __restrict__ bias, float* __restrict__ outF,
            unsigned short* __restrict__ outH, const float* __restrict__ vx,
            int Ks, int SKp, int nbP, int ldc,
            size_t batchA, size_t batchB, int batchBias)
{
    constexpr int THREADS = (TM == 256) ? 512 : 256;
    constexpr int ROWS = TM + 128;
    constexpr int CH = ROWS * 4 / THREADS;
    constexpr int WMC = TM / 64;
    constexpr int ABUF = TM * LDK;
    constexpr int BBUF = 128 * LDK;

    extern __shared__ __align__(16) unsigned short smem[];
    unsigned short* sA = smem;                 // [2][ABUF]
    unsigned short* sB = smem + 2 * ABUF;      // [2][BBUF]

    const int tid = threadIdx.x;
    const int wid = tid >> 5, lane = tid & 31;
    const int m0 = blockIdx.y * TM;
    const int n0 = blockIdx.x * 128;
    const int z  = blockIdx.z;
    const int wm = (wid % WMC) * 64;
    const int wn = (wid / WMC) * 32;

    const int NIT = Ks / 32;
    const int koff = (MODE == 4) ? z * NIT : 0;

    A  += (size_t)z * batchA;
    Bm += (size_t)z * batchB;
    if (MODE == 2 || MODE == 3) bias += (size_t)z * batchBias;

    // staging maps (cp.async)
    const unsigned short* gp[CH];
    uint32_t sdA[CH];
    bool isA_[CH];
    #pragma unroll
    for (int t = 0; t < CH; t++) {
        int id = tid + t * THREADS;
        int r = id >> 2, q = id & 3;
        if (r < TM) {
            gp[t] = A + (size_t)(m0 + r) * SKp + q * 8;
            sdA[t] = smem_u32(sA + r * LDK + q * 8);
            isA_[t] = true;
        } else {
            gp[t] = Bm + (size_t)(n0 + r - TM) * SKp + q * 8;
            sdA[t] = smem_u32(sB + (r - TM) * LDK + q * 8);
            isA_[t] = false;
        }
    }

    float acc[4][4][4];
    #pragma unroll
    for (int i = 0; i < 4; i++)
        #pragma unroll
        for (int j = 0; j < 4; j++)
            #pragma unroll
            for (int q = 0; q < 4; q++) acc[i][j][q] = 0.f;

    const uint32_t sA_base = smem_u32(sA);
    const uint32_t sB_base = smem_u32(sB);
    const int aRow = wm + (lane & 15);
    const int aKof = (lane >> 4) * 8;
    const int bRow = wn + ((lane & 7) | ((lane >> 4) << 3));
    const int bKof = ((lane >> 3) & 1) * 8;

    auto stage = [&](int k, int buf) {
        int kg = k + koff;
        int kA = kg;
        int kB = (TERMS == 2) ? ((kg < nbP) ? kg : kg - nbP) : kg;
        #pragma unroll
        for (int t = 0; t < CH; t++) {
            const unsigned short* src = gp[t] + (size_t)(isA_[t] ? kA : kB) * 32;
            uint32_t dst = sdA[t] + (uint32_t)buf * (isA_[t] ? ABUF : BBUF) * 2;
            cp_async16(dst, src);
        }
        CP_COMMIT();
    };

    stage(0, 0);
    CP_WAIT0();
    __syncthreads();

    for (int it = 0; it < NIT; it++) {
        const int cur = it & 1;
        const bool more = (it + 1) < NIT;
        if (more) stage(it + 1, cur ^ 1);

        const uint32_t aBuf = sA_base + cur * (ABUF * 2);
        const uint32_t bBuf = sB_base + cur * (BBUF * 2);
        #pragma unroll
        for (int ks = 0; ks < 32; ks += 16) {
            uint32_t af[4][4], bf[4][2];
            #pragma unroll
            for (int mt = 0; mt < 4; mt++)
                ldmatrix_x4(af[mt][0], af[mt][1], af[mt][2], af[mt][3],
                            aBuf + (uint32_t)(((aRow + mt * 16) * LDK + ks + aKof) * 2));
            #pragma unroll
            for (int np = 0; np < 2; np++)
                ldmatrix_x4(bf[np * 2][0], bf[np * 2][1], bf[np * 2 + 1][0], bf[np * 2 + 1][1],
                            bBuf + (uint32_t)(((bRow + np * 16) * LDK + ks + bKof) * 2));
            #pragma unroll
            for (int mt = 0; mt < 4; mt++)
                #pragma unroll
                for (int nt = 0; nt < 4; nt++)
                    mma_16816(acc[mt][nt], af[mt], bf[nt]);
        }
        if (more) CP_WAIT0();
        __syncthreads();
    }

    // epilogue
    const int erow = lane >> 2;
    const int ecol = (lane & 3) * 2;
    #pragma unroll
    for (int mt = 0; mt < 4; mt++) {
        #pragma unroll
        for (int nt = 0; nt < 4; nt++) {
            const int r0 = m0 + wm + mt * 16 + erow;
            const int c  = n0 + wn + nt * 8 + ecol;
            const float* v = acc[mt][nt];
            if (MODE == 0) {
                #pragma unroll
                for (int hr = 0; hr < 2; hr++) {
                    uint32_t pk = (uint32_t)__half_as_ushort(__float2half_rn(v[hr * 2]))
                                | ((uint32_t)__half_as_ushort(__float2half_rn(v[hr * 2 + 1])) << 16);
                    *(uint32_t*)&outH[(size_t)(r0 + hr * 8) * ldc + c] = pk;
                }
            } else if (MODE == 2) {
                float b0 = bias[c], b1 = bias[c + 1];
                int zz = c >> 9, f = c & 511;
                #pragma unroll
                for (int hr = 0; hr < 2; hr++) {
                    float y0 = fmaxf(v[hr * 2] + b0, 0.f);
                    float y1 = fmaxf(v[hr * 2 + 1] + b1, 0.f);
                    uint32_t pk = (uint32_t)__half_as_ushort(__float2half_rn(y0))
                                | ((uint32_t)__half_as_ushort(__float2half_rn(y1)) << 16);
                    *(uint32_t*)&outH[((size_t)zz * 1024 + (r0 + hr * 8)) * 512 + f] = pk;
                }
            } else if (MODE == 3) {
                // G2: scatter fp16 va into X16 at the <=3 shifted positions.
                // X16[(b*8+i)*1536 + di*512 + c] with i = z+dd, di = 1-dd.
                float b0 = bias[c], b1 = bias[c + 1];
                #pragma unroll
                for (int hr = 0; hr < 2; hr++) {
                    int b = r0 + hr * 8;
                    float s0 = vx[(size_t)b * 512 + c];
                    float s1 = vx[(size_t)b * 512 + c + 1];
                    float y0 = s0 * fmaxf(v[hr * 2] + b0, 0.f);
                    float y1 = s1 * fmaxf(v[hr * 2 + 1] + b1, 0.f);
                    uint32_t pk = (uint32_t)__half_as_ushort(__float2half_rn(y0))
                                | ((uint32_t)__half_as_ushort(__float2half_rn(y1)) << 16);
                    #pragma unroll
                    for (int dd = -1; dd <= 1; dd++) {
                        int i = z + dd;
                        if (i >= 0 && i <= 7) {
                            int di = 1 - dd;
                            *(uint32_t*)&outH[(size_t)(b * 8 + i) * 1536 + di * 512 + c] = pk;
                        }
                    }
                }
            } else {  // MODE 4: raw float partial, z-offset
                float* o = outF + (size_t)z * batchBias;
                *(float2*)&o[(size_t)r0 * ldc + c] = make_float2(v[0], v[1]);
                *(float2*)&o[(size_t)(r0 + 8) * ldc + c] = make_float2(v[2], v[3]);
            }
        }
    }
}

// ---------------- pool: Y16 -> p3 (exact split) ----------------
__global__ void pool_split_kernel(const unsigned short* __restrict__ Y,
                                  const float* __restrict__ c1b) {
    int idx = blockIdx.x * blockDim.x + threadIdx.x;   // 1024*512
    int c = idx & 511, b = idx >> 9;
    float bias = c1b[c];
    float m00 = -1e30f, m01 = -1e30f, m10 = -1e30f, m11 = -1e30f;
    #pragma unroll
    for (int i = 0; i < 8; i++) {
        size_t base = (size_t)(b * 8 + i) * 1536;
        float yM = __half2float(__ushort_as_half(Y[base + c]));
        float yB = __half2float(__ushort_as_half(Y[base + 512 + c]));
        float yC = __half2float(__ushort_as_half(Y[base + 1024 + c]));
        float vL = fmaxf(yM - yB, yM);
        float vR = fmaxf(yM - yC, yM);
        if (i < 4) { m00 = fmaxf(m00, vL); m01 = fmaxf(m01, vR); }
        else       { m10 = fmaxf(m10, vL); m11 = fmaxf(m11, vR); }
    }
    float p[4] = {m00 + bias, m01 + bias, m10 + bias, m11 + bias};
    ushort4 hi, lo;
    split_hi_lo(p[0], hi.x, lo.x);
    split_hi_lo(p[1], hi.y, lo.y);
    split_hi_lo(p[2], hi.z, lo.z);
    split_hi_lo(p[3], hi.w, lo.w);
    size_t e0 = (size_t)b * 4096 + c * 4;
    *(ushort4*)(g_p3 + e0)        = hi;
    *(ushort4*)(g_p3 + e0 + 2048) = lo;
}

// ---------------- G3 reduce: sum 4 partials + bias, relu ----------------
__global__ void reduce_relu_kernel(const float* __restrict__ parts,
                                   const float* __restrict__ bias,
                                   float* __restrict__ out) {
    int idx = blockIdx.x * blockDim.x + threadIdx.x;   // 1024*512/4
    size_t e = (size_t)idx * 4;
    int c = (int)(e & 511);
    float4 a = *(const float4*)(parts + e);
    float4 b = *(const float4*)(parts + e + 524288);
    float4 d = *(const float4*)(parts + e + 2 * 524288);
    float4 f = *(const float4*)(parts + e + 3 * 524288);
    float4 bi = *(const float4*)(bias + c);
    float4 r;
    r.x = fmaxf(a.x + b.x + d.x + f.x + bi.x, 0.f);
    r.y = fmaxf(a.y + b.y + d.y + f.y + bi.y, 0.f);
    r.z = fmaxf(a.z + b.z + d.z + f.z + bi.z, 0.f);
    r.w = fmaxf(a.w + b.w + d.w + f.w + bi.w, 0.f);
    *(float4*)(out + e) = r;
}

// ---------------- launch ----------------
extern "C" void kernel_launch(void* const* d_in, const int* in_sizes, int n_in,
                              void* d_out, int out_size) {
    (void)in_sizes; (void)n_in; (void)out_size;
    const float* vx  = (const float*)d_in[0];
    const float* ax  = (const float*)d_in[1];
    const float* W1  = (const float*)d_in[2];
    const float* b1  = (const float*)d_in[3];
    const float* W2  = (const float*)d_in[4];
    const float* b2  = (const float*)d_in[5];
    const float* c1w = (const float*)d_in[6];
    const float* c1b = (const float*)d_in[7];
    const float* c2w = (const float*)d_in[8];
    const float* c2b = (const float*)d_in[9];
    float* out = (float*)d_out;

    void *p_xcat16, *p_W16, *p_h16, *p_W216, *p_X16, *p_W3, *p_Y16, *p_p3, *p_A23, *p_part;
    cudaGetSymbolAddress(&p_xcat16, g_xcat16);
    cudaGetSymbolAddress(&p_W16,    g_W16);
    cudaGetSymbolAddress(&p_h16,    g_h16);
    cudaGetSymbolAddress(&p_W216,   g_W216);
    cudaGetSymbolAddress(&p_X16,    g_X16);
    cudaGetSymbolAddress(&p_W3,     g_W3);
    cudaGetSymbolAddress(&p_Y16,    g_Y16);
    cudaGetSymbolAddress(&p_p3,     g_p3);
    cudaGetSymbolAddress(&p_A23,    g_A23);
    cudaGetSymbolAddress(&p_part,   g_part);

    const int SM256 = (2 * 256 + 2 * 128) * LDK * 2;  // 61440
    const int SM128 = (2 * 128 + 2 * 128) * LDK * 2;  // 40960
    cudaFuncSetAttribute((const void*)hmma_kernel<128, 2, 1>, cudaFuncAttributeMaxDynamicSharedMemorySize, SM128);
    cudaFuncSetAttribute((const void*)hmma_kernel<128, 3, 1>, cudaFuncAttributeMaxDynamicSharedMemorySize, SM128);
    cudaFuncSetAttribute((const void*)hmma_kernel<256, 0, 1>, cudaFuncAttributeMaxDynamicSharedMemorySize, SM256);
    cudaFuncSetAttribute((const void*)hmma_kernel<128, 4, 2>, cudaFuncAttributeMaxDynamicSharedMemorySize, SM128);

    // operand builders
    concat16_kernel<<<512, 256>>>(vx, ax);                                  // xcat16
    build16_kernel<<<2048, 256>>>(W1, (unsigned short*)p_W16, 4096 * 128);  // W1 fp16
    build16_kernel<<<1024, 256>>>(W2, (unsigned short*)p_W216, 4096 * 64);  // W2 fp16
    pre_A2_kernel<<<4096, 256>>>(c2w);                                      // A2 split
    build_w3_kernel<<<1152, 256>>>(c1w);                                    // W3 fp16

    // GEMM1 (1-term, TM=128 occ2): h16 = fp16(relu(xcat16*W16^T + b1)); K=1024
    hmma_kernel<128, 2, 1><<<dim3(32, 8), 256, SM128>>>(
        (const unsigned short*)p_xcat16, (const unsigned short*)p_W16, b1,
        nullptr, (unsigned short*)p_h16, nullptr,
        1024, 1024, 0, 0, 0, 0, 0);

    // GEMM2 (1-term, TM=128 occ2, batch z): scatter X16 = shifted fp16 va; K=512
    hmma_kernel<128, 3, 1><<<dim3(4, 8, 8), 256, SM128>>>(
        (const unsigned short*)p_h16, (const unsigned short*)p_W216, b2,
        nullptr, (unsigned short*)p_X16, vx,
        512, 512, 0, 0, (size_t)1024 * 512, (size_t)512 * 512, 512);

    // conv GEMM (1-term): Y16 = X16*W3^T; K=1536
    hmma_kernel<256, 0, 1><<<dim3(12, 32), 512, SM256>>>(
        (const unsigned short*)p_X16, (const unsigned short*)p_W3, nullptr,
        nullptr, (unsigned short*)p_Y16, nullptr,
        1536, 1536, 0, 1536, 0, 0, 0);

    // pool -> p3 (exact split)
    pool_split_kernel<<<2048, 256>>>((const unsigned short*)p_Y16, c1b);

    // GEMM3 (2-term, split-K=4): part_z = p*A2h^T over K-slice z; logical K=4096
    hmma_kernel<128, 4, 2><<<dim3(4, 8, 4), 256, SM128>>>(
        (const unsigned short*)p_p3, (const unsigned short*)p_A23, nullptr,
        (float*)p_part, nullptr, nullptr,
        1024, 4096, 64, 512, 0, 0, 1024 * 512);

    // reduce partials + bias + relu -> out
    reduce_relu_kernel<<<512, 256>>>((const float*)p_part, c2b, out);
}

// round 14
// speedup vs baseline: 2.5916x; 1.1106x over previous
#include <cuda_runtime.h>
#include <cuda_fp16.h>
#include <cstdint>
#include <cstddef>

// B=1024, F=512, N=8 — HMMA fp16 (fp32 accum), all GEMMs 1-term fp16.
// G1: h16 = fp16(relu(x*W1+b1)).  G2: epilogue scatters di-shifted conv operand X16.
// conv (TM=128 occ2): Y16 = X16*W3^T.  pool -> fp16 p16.
// G3: 1-term split-K=4 (p16 × A2h) + reduce.  Error ~4.8e-4 (quadrature).

#define LDK 40   // smem row stride in halves (80B, conflict-free ldmatrix)

// ---------------- static scratch ----------------
__device__ unsigned short g_xcat16[(size_t)1024 * 1024];  // fp16 [vx|ax]
__device__ unsigned short g_W16[(size_t)4096 * 1024];     // fp16 W1
__device__ unsigned short g_h16[(size_t)8 * 1024 * 512];  // fp16 h, [z][b][f]
__device__ unsigned short g_W216[(size_t)4096 * 512];     // fp16 W2
__device__ unsigned short g_X16[(size_t)8192 * 1536];     // conv A (scatter-written;
                                                          // boundary blocks stay bss-zero)
__device__ unsigned short g_W3[(size_t)1536 * 1536];      // conv B, fp16
__device__ unsigned short g_Y16[(size_t)8192 * 1536];     // conv out, fp16
__device__ unsigned short g_p16[(size_t)1024 * 2048];     // pooled, fp16
__device__ unsigned short g_A216[(size_t)512 * 2048];     // conv2-collapsed, fp16
__device__ float g_part[(size_t)4 * 1024 * 512];          // G3 split-K partials

// ---------------- helpers ----------------
union Pack8 { unsigned short s[8]; uint4 v; };
__device__ __forceinline__ uint32_t smem_u32(const void* p) {
    uint32_t a;
    asm("{ .reg .u64 t; cvta.to.shared.u64 t, %1; cvt.u32.u64 %0, t; }" : "=r"(a) : "l"(p));
    return a;
}
__device__ __forceinline__ void ldmatrix_x4(uint32_t& r0, uint32_t& r1, uint32_t& r2, uint32_t& r3,
                                            uint32_t addr) {
    asm volatile("ldmatrix.sync.aligned.m8n8.x4.shared.b16 {%0,%1,%2,%3}, [%4];"
                 : "=r"(r0), "=r"(r1), "=r"(r2), "=r"(r3) : "r"(addr));
}
__device__ __forceinline__ void mma_16816(float* c, const uint32_t* a, const uint32_t* b) {
    asm volatile("mma.sync.aligned.m16n8k16.row.col.f32.f16.f16.f32 "
                 "{%0,%1,%2,%3}, {%4,%5,%6,%7}, {%8,%9}, {%0,%1,%2,%3};"
                 : "+f"(c[0]), "+f"(c[1]), "+f"(c[2]), "+f"(c[3])
                 : "r"(a[0]), "r"(a[1]), "r"(a[2]), "r"(a[3]), "r"(b[0]), "r"(b[1]));
}
__device__ __forceinline__ void cp_async16(uint32_t dst, const void* src) {
    asm volatile("cp.async.cg.shared.global [%0], [%1], 16;" :: "r"(dst), "l"(src));
}
#define CP_COMMIT() asm volatile("cp.async.commit_group;" ::: "memory")
#define CP_WAIT0()  asm volatile("cp.async.wait_group 0;" ::: "memory")

// ---------------- operand builders ----------------
__global__ void concat16_kernel(const float* __restrict__ vx, const float* __restrict__ ax) {
    int idx = blockIdx.x * blockDim.x + threadIdx.x;  // 1024*128
    int kv = idx & 127, b = idx >> 7;
    const float* src = (kv < 64) ? (vx + (size_t)b * 512 + kv * 8)
                                 : (ax + (size_t)b * 512 + (kv - 64) * 8);
    float4 x0 = *(const float4*)src, x1 = *(const float4*)(src + 4);
    float vals[8] = {x0.x, x0.y, x0.z, x0.w, x1.x, x1.y, x1.z, x1.w};
    Pack8 h;
    #pragma unroll
    for (int j = 0; j < 8; j++) h.s[j] = __half_as_ushort(__float2half_rn(vals[j]));
    *(uint4*)(g_xcat16 + (size_t)b * 1024 + kv * 8) = h.v;
}

__global__ void build16_kernel(const float* __restrict__ src, unsigned short* __restrict__ dst,
                               int n8) {
    int idx = blockIdx.x * blockDim.x + threadIdx.x;
    if (idx >= n8) return;
    const float* s = src + (size_t)idx * 8;
    float4 x0 = *(const float4*)s, x1 = *(const float4*)(s + 4);
    float vals[8] = {x0.x, x0.y, x0.z, x0.w, x1.x, x1.y, x1.z, x1.w};
    Pack8 h;
    #pragma unroll
    for (int j = 0; j < 8; j++) h.s[j] = __half_as_ushort(__float2half_rn(vals[j]));
    *(uint4*)(dst + (size_t)idx * 8) = h.v;
}

// conv2+mean collapse -> plain fp16: g_A216[c][f*4+q]
__global__ void pre_A2_kernel(const float* __restrict__ w2) {
    int idx = blockIdx.x * blockDim.x + threadIdx.x;  // 512*512*4
    int q = idx & 3;
    int cf = idx >> 2;
    int f = cf & 511;
    int c = cf >> 9;
    int ip = q >> 1, jp = q & 1;
    const float* wb = w2 + (size_t)(c * 512 + f) * 9;
    float s = 0.f;
    #pragma unroll
    for (int i = 0; i < 2; i++)
        #pragma unroll
        for (int j = 0; j < 2; j++)
            s += wb[(ip - i + 1) * 3 + (jp - j + 1)];
    g_A216[(size_t)c * 2048 + f * 4 + q] = __half_as_ushort(__float2half_rn(0.25f * s));
}

// conv B: W3[n=t*512+c][di*512+f], fp16, row stride 1536
__global__ void build_w3_kernel(const float* __restrict__ c1w) {
    int idx = blockIdx.x * blockDim.x + threadIdx.x;   // 1536*3*64
    int fg = idx & 63;
    int di = (idx >> 6) % 3;
    int n  = idx / 192;
    int t = n >> 9, c = n & 511;
    Pack8 hi;
    #pragma unroll
    for (int j = 0; j < 8; j++) {
        int f = fg * 8 + j;
        size_t base = ((size_t)(c * 512 + f) * 3 + di) * 3;
        float w;
        if (t == 0)      w = c1w[base] + c1w[base + 1] + c1w[base + 2];
        else if (t == 1) w = c1w[base];
        else             w = c1w[base + 2];
        hi.s[j] = __half_as_ushort(__float2half_rn(w));
    }
    *(uint4*)(g_W3 + (size_t)n * 1536 + di * 512 + fg * 8) = hi.v;
}

// ---------------- unified HMMA GEMM ----------------
// TERMS==1: plain GEMM, kA=kB=kg (kg = k + koff for split-K).
// MODE 0: fp16 store (conv Y)       MODE 2: fp16 h store [z][b][f] (G1)
// MODE 3: X16 scatter epilogue (G2) MODE 4: raw float partial store, z-offset (G3)
template <int TM, int MODE, int TERMS>
__global__ void __launch_bounds__((TM == 256) ? 512 : 256, (TM == 256) ? 1 : 2)
hmma_kernel(const unsigned short* __restrict__ A, const unsigned short* __restrict__ Bm,
            const float* __restrict__ bias, float* __restrict__ outF,
            unsigned short* __restrict__ outH, const float* __restrict__ vx,
            int Ks, int SKp, int nbP, int ldc,
            size_t batchA, size_t batchB, int batchBias)
{
    constexpr int THREADS = (TM == 256) ? 512 : 256;
    constexpr int ROWS = TM + 128;
    constexpr int CH = ROWS * 4 / THREADS;
    constexpr int WMC = TM / 64;
    constexpr int ABUF = TM * LDK;
    constexpr int BBUF = 128 * LDK;

    extern __shared__ __align__(16) unsigned short smem[];
    unsigned short* sA = smem;                 // [2][ABUF]
    unsigned short* sB = smem + 2 * ABUF;      // [2][BBUF]

    const int tid = threadIdx.x;
    const int wid = tid >> 5, lane = tid & 31;
    const int m0 = blockIdx.y * TM;
    const int n0 = blockIdx.x * 128;
    const int z  = blockIdx.z;
    const int wm = (wid % WMC) * 64;
    const int wn = (wid / WMC) * 32;

    const int NIT = Ks / 32;
    const int koff = (MODE == 4) ? z * NIT : 0;

    A  += (size_t)z * batchA;
    Bm += (size_t)z * batchB;
    if (MODE == 2 || MODE == 3) bias += (size_t)z * batchBias;

    // staging maps (cp.async)
    const unsigned short* gp[CH];
    uint32_t sdA[CH];
    bool isA_[CH];
    #pragma unroll
    for (int t = 0; t < CH; t++) {
        int id = tid + t * THREADS;
        int r = id >> 2, q = id & 3;
        if (r < TM) {
            gp[t] = A + (size_t)(m0 + r) * SKp + q * 8;
            sdA[t] = smem_u32(sA + r * LDK + q * 8);
            isA_[t] = true;
        } else {
            gp[t] = Bm + (size_t)(n0 + r - TM) * SKp + q * 8;
            sdA[t] = smem_u32(sB + (r - TM) * LDK + q * 8);
            isA_[t] = false;
        }
    }

    float acc[4][4][4];
    #pragma unroll
    for (int i = 0; i < 4; i++)
        #pragma unroll
        for (int j = 0; j < 4; j++)
            #pragma unroll
            for (int q = 0; q < 4; q++) acc[i][j][q] = 0.f;

    const uint32_t sA_base = smem_u32(sA);
    const uint32_t sB_base = smem_u32(sB);
    const int aRow = wm + (lane & 15);
    const int aKof = (lane >> 4) * 8;
    const int bRow = wn + ((lane & 7) | ((lane >> 4) << 3));
    const int bKof = ((lane >> 3) & 1) * 8;

    auto stage = [&](int k, int buf) {
        int kg = k + koff;
        int kA = kg;
        int kB = (TERMS == 2) ? ((kg < nbP) ? kg : kg - nbP) : kg;
        #pragma unroll
        for (int t = 0; t < CH; t++) {
            const unsigned short* src = gp[t] + (size_t)(isA_[t] ? kA : kB) * 32;
            uint32_t dst = sdA[t] + (uint32_t)buf * (isA_[t] ? ABUF : BBUF) * 2;
            cp_async16(dst, src);
        }
        CP_COMMIT();
    };

    stage(0, 0);
    CP_WAIT0();
    __syncthreads();

    for (int it = 0; it < NIT; it++) {
        const int cur = it & 1;
        const bool more = (it + 1) < NIT;
        if (more) stage(it + 1, cur ^ 1);

        const uint32_t aBuf = sA_base + cur * (ABUF * 2);
        const uint32_t bBuf = sB_base + cur * (BBUF * 2);
        #pragma unroll
        for (int ks = 0; ks < 32; ks += 16) {
            uint32_t af[4][4], bf[4][2];
            #pragma unroll
            for (int mt = 0; mt < 4; mt++)
                ldmatrix_x4(af[mt][0], af[mt][1], af[mt][2], af[mt][3],
                            aBuf + (uint32_t)(((aRow + mt * 16) * LDK + ks + aKof) * 2));
            #pragma unroll
            for (int np = 0; np < 2; np++)
                ldmatrix_x4(bf[np * 2][0], bf[np * 2][1], bf[np * 2 + 1][0], bf[np * 2 + 1][1],
                            bBuf + (uint32_t)(((bRow + np * 16) * LDK + ks + bKof) * 2));
            #pragma unroll
            for (int mt = 0; mt < 4; mt++)
                #pragma unroll
                for (int nt = 0; nt < 4; nt++)
                    mma_16816(acc[mt][nt], af[mt], bf[nt]);
        }
        if (more) CP_WAIT0();
        __syncthreads();
    }

    // epilogue
    const int erow = lane >> 2;
    const int ecol = (lane & 3) * 2;
    #pragma unroll
    for (int mt = 0; mt < 4; mt++) {
        #pragma unroll
        for (int nt = 0; nt < 4; nt++) {
            const int r0 = m0 + wm + mt * 16 + erow;
            const int c  = n0 + wn + nt * 8 + ecol;
            const float* v = acc[mt][nt];
            if (MODE == 0) {
                #pragma unroll
                for (int hr = 0; hr < 2; hr++) {
                    uint32_t pk = (uint32_t)__half_as_ushort(__float2half_rn(v[hr * 2]))
                                | ((uint32_t)__half_as_ushort(__float2half_rn(v[hr * 2 + 1])) << 16);
                    *(uint32_t*)&outH[(size_t)(r0 + hr * 8) * ldc + c] = pk;
                }
            } else if (MODE == 2) {
                float b0 = bias[c], b1 = bias[c + 1];
                int zz = c >> 9, f = c & 511;
                #pragma unroll
                for (int hr = 0; hr < 2; hr++) {
                    float y0 = fmaxf(v[hr * 2] + b0, 0.f);
                    float y1 = fmaxf(v[hr * 2 + 1] + b1, 0.f);
                    uint32_t pk = (uint32_t)__half_as_ushort(__float2half_rn(y0))
                                | ((uint32_t)__half_as_ushort(__float2half_rn(y1)) << 16);
                    *(uint32_t*)&outH[((size_t)zz * 1024 + (r0 + hr * 8)) * 512 + f] = pk;
                }
            } else if (MODE == 3) {
                // G2: scatter fp16 va into X16 at the <=3 shifted positions.
                float b0 = bias[c], b1 = bias[c + 1];
                #pragma unroll
                for (int hr = 0; hr < 2; hr++) {
                    int b = r0 + hr * 8;
                    float s0 = vx[(size_t)b * 512 + c];
                    float s1 = vx[(size_t)b * 512 + c + 1];
                    float y0 = s0 * fmaxf(v[hr * 2] + b0, 0.f);
                    float y1 = s1 * fmaxf(v[hr * 2 + 1] + b1, 0.f);
                    uint32_t pk = (uint32_t)__half_as_ushort(__float2half_rn(y0))
                                | ((uint32_t)__half_as_ushort(__float2half_rn(y1)) << 16);
                    #pragma unroll
                    for (int dd = -1; dd <= 1; dd++) {
                        int i = z + dd;
                        if (i >= 0 && i <= 7) {
                            int di = 1 - dd;
                            *(uint32_t*)&outH[(size_t)(b * 8 + i) * 1536 + di * 512 + c] = pk;
                        }
                    }
                }
            } else {  // MODE 4: raw float partial, z-offset
                float* o = outF + (size_t)z * batchBias;
                *(float2*)&o[(size_t)r0 * ldc + c] = make_float2(v[0], v[1]);
                *(float2*)&o[(size_t)(r0 + 8) * ldc + c] = make_float2(v[2], v[3]);
            }
        }
    }
}

// ---------------- pool: Y16 -> p16 (fp16) ----------------
__global__ void pool16_kernel(const unsigned short* __restrict__ Y,
                              const float* __restrict__ c1b) {
    int idx = blockIdx.x * blockDim.x + threadIdx.x;   // 1024*512
    int c = idx & 511, b = idx >> 9;
    float bias = c1b[c];
    float m00 = -1e30f, m01 = -1e30f, m10 = -1e30f, m11 = -1e30f;
    #pragma unroll
    for (int i = 0; i < 8; i++) {
        size_t base = (size_t)(b * 8 + i) * 1536;
        float yM = __half2float(__ushort_as_half(Y[base + c]));
        float yB = __half2float(__ushort_as_half(Y[base + 512 + c]));
        float yC = __half2float(__ushort_as_half(Y[base + 1024 + c]));
        float vL = fmaxf(yM - yB, yM);
        float vR = fmaxf(yM - yC, yM);
        if (i < 4) { m00 = fmaxf(m00, vL); m01 = fmaxf(m01, vR); }
        else       { m10 = fmaxf(m10, vL); m11 = fmaxf(m11, vR); }
    }
    ushort4 o;
    o.x = __half_as_ushort(__float2half_rn(m00 + bias));
    o.y = __half_as_ushort(__float2half_rn(m01 + bias));
    o.z = __half_as_ushort(__float2half_rn(m10 + bias));
    o.w = __half_as_ushort(__float2half_rn(m11 + bias));
    *(ushort4*)(g_p16 + (size_t)b * 2048 + c * 4) = o;
}

// ---------------- G3 reduce: sum 4 partials + bias, relu ----------------
__global__ void reduce_relu_kernel(const float* __restrict__ parts,
                                   const float* __restrict__ bias,
                                   float* __restrict__ out) {
    int idx = blockIdx.x * blockDim.x + threadIdx.x;   // 1024*512/4
    size_t e = (size_t)idx * 4;
    int c = (int)(e & 511);
    float4 a = *(const float4*)(parts + e);
    float4 b = *(const float4*)(parts + e + 524288);
    float4 d = *(const float4*)(parts + e + 2 * 524288);
    float4 f = *(const float4*)(parts + e + 3 * 524288);
    float4 bi = *(const float4*)(bias + c);
    float4 r;
    r.x = fmaxf(a.x + b.x + d.x + f.x + bi.x, 0.f);
    r.y = fmaxf(a.y + b.y + d.y + f.y + bi.y, 0.f);
    r.z = fmaxf(a.z + b.z + d.z + f.z + bi.z, 0.f);
    r.w = fmaxf(a.w + b.w + d.w + f.w + bi.w, 0.f);
    *(float4*)(out + e) = r;
}

// ---------------- launch ----------------
extern "C" void kernel_launch(void* const* d_in, const int* in_sizes, int n_in,
                              void* d_out, int out_size) {
    (void)in_sizes; (void)n_in; (void)out_size;
    const float* vx  = (const float*)d_in[0];
    const float* ax  = (const float*)d_in[1];
    const float* W1  = (const float*)d_in[2];
    const float* b1  = (const float*)d_in[3];
    const float* W2  = (const float*)d_in[4];
    const float* b2  = (const float*)d_in[5];
    const float* c1w = (const float*)d_in[6];
    const float* c1b = (const float*)d_in[7];
    const float* c2w = (const float*)d_in[8];
    const float* c2b = (const float*)d_in[9];
    float* out = (float*)d_out;

    void *p_xcat16, *p_W16, *p_h16, *p_W216, *p_X16, *p_W3, *p_Y16, *p_p16, *p_A216, *p_part;
    cudaGetSymbolAddress(&p_xcat16, g_xcat16);
    cudaGetSymbolAddress(&p_W16,    g_W16);
    cudaGetSymbolAddress(&p_h16,    g_h16);
    cudaGetSymbolAddress(&p_W216,   g_W216);
    cudaGetSymbolAddress(&p_X16,    g_X16);
    cudaGetSymbolAddress(&p_W3,     g_W3);
    cudaGetSymbolAddress(&p_Y16,    g_Y16);
    cudaGetSymbolAddress(&p_p16,    g_p16);
    cudaGetSymbolAddress(&p_A216,   g_A216);
    cudaGetSymbolAddress(&p_part,   g_part);

    const int SM128 = (2 * 128 + 2 * 128) * LDK * 2;  // 40960
    cudaFuncSetAttribute((const void*)hmma_kernel<128, 2, 1>, cudaFuncAttributeMaxDynamicSharedMemorySize, SM128);
    cudaFuncSetAttribute((const void*)hmma_kernel<128, 3, 1>, cudaFuncAttributeMaxDynamicSharedMemorySize, SM128);
    cudaFuncSetAttribute((const void*)hmma_kernel<128, 0, 1>, cudaFuncAttributeMaxDynamicSharedMemorySize, SM128);
    cudaFuncSetAttribute((const void*)hmma_kernel<128, 4, 1>, cudaFuncAttributeMaxDynamicSharedMemorySize, SM128);

    // operand builders
    concat16_kernel<<<512, 256>>>(vx, ax);                                  // xcat16
    build16_kernel<<<2048, 256>>>(W1, (unsigned short*)p_W16, 4096 * 128);  // W1 fp16
    build16_kernel<<<1024, 256>>>(W2, (unsigned short*)p_W216, 4096 * 64);  // W2 fp16
    pre_A2_kernel<<<4096, 256>>>(c2w);                                      // A2 fp16
    build_w3_kernel<<<1152, 256>>>(c1w);                                    // W3 fp16

    // GEMM1 (1-term, TM=128 occ2): h16 = fp16(relu(xcat16*W16^T + b1)); K=1024
    hmma_kernel<128, 2, 1><<<dim3(32, 8), 256, SM128>>>(
        (const unsigned short*)p_xcat16, (const unsigned short*)p_W16, b1,
        nullptr, (unsigned short*)p_h16, nullptr,
        1024, 1024, 0, 0, 0, 0, 0);

    // GEMM2 (1-term, TM=128 occ2, batch z): scatter X16 = shifted fp16 va; K=512
    hmma_kernel<128, 3, 1><<<dim3(4, 8, 8), 256, SM128>>>(
        (const unsigned short*)p_h16, (const unsigned short*)p_W216, b2,
        nullptr, (unsigned short*)p_X16, vx,
        512, 512, 0, 0, (size_t)1024 * 512, (size_t)512 * 512, 512);

    // conv GEMM (1-term, TM=128 occ2): Y16 = X16*W3^T; K=1536
    hmma_kernel<128, 0, 1><<<dim3(12, 64), 256, SM128>>>(
        (const unsigned short*)p_X16, (const unsigned short*)p_W3, nullptr,
        nullptr, (unsigned short*)p_Y16, nullptr,
        1536, 1536, 0, 1536, 0, 0, 0);

    // pool -> p16 (fp16)
    pool16_kernel<<<2048, 256>>>((const unsigned short*)p_Y16, c1b);

    // GEMM3 (1-term, split-K=4): part_z = p16*A216^T over K-slice z; K=2048
    hmma_kernel<128, 4, 1><<<dim3(4, 8, 4), 256, SM128>>>(
        (const unsigned short*)p_p16, (const unsigned short*)p_A216, nullptr,
        (float*)p_part, nullptr, nullptr,
        512, 2048, 0, 512, 0, 0, 1024 * 512);

    // reduce partials + bias + relu -> out
    reduce_relu_kernel<<<512, 256>>>((const float*)p_part, c2b, out);
}

// round 15
// speedup vs baseline: 2.5942x; 1.0010x over previous
#include <cuda_runtime.h>
#include <cuda_fp16.h>
#include <cstdint>
#include <cstddef>

// B=1024, F=512, N=8 — HMMA fp16 (fp32 accum), all GEMMs 1-term fp16.
// G1: h16 = fp16(relu(x*W1+b1)).  G2: epilogue scatters di-shifted conv operand X16.
// conv (persistent 296 CTAs): Y16 = X16*W3^T.  pool (vectorized) -> fp16 p16.
// G3: 1-term split-K=4 + reduce.  Builders fused into one kernel.

#define LDK 40   // smem row stride in halves (80B, conflict-free ldmatrix)

// ---------------- static scratch ----------------
__device__ unsigned short g_xcat16[(size_t)1024 * 1024];  // fp16 [vx|ax]
__device__ unsigned short g_W16[(size_t)4096 * 1024];     // fp16 W1
__device__ unsigned short g_h16[(size_t)8 * 1024 * 512];  // fp16 h, [z][b][f]
__device__ unsigned short g_W216[(size_t)4096 * 512];     // fp16 W2
__device__ unsigned short g_X16[(size_t)8192 * 1536];     // conv A (scatter-written;
                                                          // boundary blocks stay bss-zero)
__device__ unsigned short g_W3[(size_t)1536 * 1536];      // conv B, fp16
__device__ unsigned short g_Y16[(size_t)8192 * 1536];     // conv out, fp16
__device__ unsigned short g_p16[(size_t)1024 * 2048];     // pooled, fp16
__device__ unsigned short g_A216[(size_t)512 * 2048];     // conv2-collapsed, fp16
__device__ float g_part[(size_t)4 * 1024 * 512];          // G3 split-K partials

// ---------------- helpers ----------------
union Pack8 { unsigned short s[8]; uint4 v; };
__device__ __forceinline__ uint32_t smem_u32(const void* p) {
    uint32_t a;
    asm("{ .reg .u64 t; cvta.to.shared.u64 t, %1; cvt.u32.u64 %0, t; }" : "=r"(a) : "l"(p));
    return a;
}
__device__ __forceinline__ void ldmatrix_x4(uint32_t& r0, uint32_t& r1, uint32_t& r2, uint32_t& r3,
                                            uint32_t addr) {
    asm volatile("ldmatrix.sync.aligned.m8n8.x4.shared.b16 {%0,%1,%2,%3}, [%4];"
                 : "=r"(r0), "=r"(r1), "=r"(r2), "=r"(r3) : "r"(addr));
}
__device__ __forceinline__ void mma_16816(float* c, const uint32_t* a, const uint32_t* b) {
    asm volatile("mma.sync.aligned.m16n8k16.row.col.f32.f16.f16.f32 "
                 "{%0,%1,%2,%3}, {%4,%5,%6,%7}, {%8,%9}, {%0,%1,%2,%3};"
                 : "+f"(c[0]), "+f"(c[1]), "+f"(c[2]), "+f"(c[3])
                 : "r"(a[0]), "r"(a[1]), "r"(a[2]), "r"(a[3]), "r"(b[0]), "r"(b[1]));
}
__device__ __forceinline__ void cp_async16(uint32_t dst, const void* src) {
    asm volatile("cp.async.cg.shared.global [%0], [%1], 16;" :: "r"(dst), "l"(src));
}
#define CP_COMMIT() asm volatile("cp.async.commit_group;" ::: "memory")
#define CP_WAIT0()  asm volatile("cp.async.wait_group 0;" ::: "memory")

// ---------------- fused operand builders ----------------
// blocks [0,512): concat16   [512,2560): W1->fp16   [2560,3584): W2->fp16
// [3584,7680): conv2-collapse A2   [7680,8832): conv1 W3 build
__global__ void builders_kernel(const float* __restrict__ vx, const float* __restrict__ ax,
                                const float* __restrict__ W1, const float* __restrict__ W2,
                                const float* __restrict__ w2c, const float* __restrict__ c1w) {
    const int bid = blockIdx.x;
    const int tid = threadIdx.x;
    if (bid < 512) {
        int idx = bid * 256 + tid;               // 1024*128
        int kv = idx & 127, b = idx >> 7;
        const float* src = (kv < 64) ? (vx + (size_t)b * 512 + kv * 8)
                                     : (ax + (size_t)b * 512 + (kv - 64) * 8);
        float4 x0 = *(const float4*)src, x1 = *(const float4*)(src + 4);
        float vals[8] = {x0.x, x0.y, x0.z, x0.w, x1.x, x1.y, x1.z, x1.w};
        Pack8 h;
        #pragma unroll
        for (int j = 0; j < 8; j++) h.s[j] = __half_as_ushort(__float2half_rn(vals[j]));
        *(uint4*)(g_xcat16 + (size_t)b * 1024 + kv * 8) = h.v;
    } else if (bid < 3584) {
        // plain fp32->fp16 convert for W1 / W2
        const float* src; unsigned short* dst; int idx;
        if (bid < 2560) { src = W1; dst = g_W16;  idx = (bid - 512) * 256 + tid; }
        else            { src = W2; dst = g_W216; idx = (bid - 2560) * 256 + tid; }
        const float* s = src + (size_t)idx * 8;
        float4 x0 = *(const float4*)s, x1 = *(const float4*)(s + 4);
        float vals[8] = {x0.x, x0.y, x0.z, x0.w, x1.x, x1.y, x1.z, x1.w};
        Pack8 h;
        #pragma unroll
        for (int j = 0; j < 8; j++) h.s[j] = __half_as_ushort(__float2half_rn(vals[j]));
        *(uint4*)(dst + (size_t)idx * 8) = h.v;
    } else if (bid < 7680) {
        int idx = (bid - 3584) * 256 + tid;      // 512*512*4
        int q = idx & 3;
        int cf = idx >> 2;
        int f = cf & 511;
        int c = cf >> 9;
        int ip = q >> 1, jp = q & 1;
        const float* wb = w2c + (size_t)(c * 512 + f) * 9;
        float s = 0.f;
        #pragma unroll
        for (int i = 0; i < 2; i++)
            #pragma unroll
            for (int j = 0; j < 2; j++)
                s += wb[(ip - i + 1) * 3 + (jp - j + 1)];
        g_A216[(size_t)c * 2048 + f * 4 + q] = __half_as_ushort(__float2half_rn(0.25f * s));
    } else {
        int idx = (bid - 7680) * 256 + tid;      // 1536*3*64
        int fg = idx & 63;
        int di = (idx >> 6) % 3;
        int n  = idx / 192;
        int t = n >> 9, c = n & 511;
        Pack8 hi;
        #pragma unroll
        for (int j = 0; j < 8; j++) {
            int f = fg * 8 + j;
            size_t base = ((size_t)(c * 512 + f) * 3 + di) * 3;
            float w;
            if (t == 0)      w = c1w[base] + c1w[base + 1] + c1w[base + 2];
            else if (t == 1) w = c1w[base];
            else             w = c1w[base + 2];
            hi.s[j] = __half_as_ushort(__float2half_rn(w));
        }
        *(uint4*)(g_W3 + (size_t)n * 1536 + di * 512 + fg * 8) = hi.v;
    }
}

// ---------------- unified HMMA GEMM ----------------
// TERMS==1: plain GEMM, kA=kB=kg (kg = k + koff for split-K).
// MODE 0: fp16 store (conv Y)       MODE 2: fp16 h store [z][b][f] (G1)
// MODE 3: X16 scatter epilogue (G2) MODE 4: raw float partial store, z-offset (G3)
// PERSIST: 1D grid of resident CTAs loops tiles; ntiles=batchA, ntx=nbP.
template <int TM, int MODE, int TERMS, bool PERSIST>
__global__ void __launch_bounds__(256, 2)
hmma_kernel(const unsigned short* __restrict__ A, const unsigned short* __restrict__ Bm,
            const float* __restrict__ bias, float* __restrict__ outF,
            unsigned short* __restrict__ outH, const float* __restrict__ vx,
            int Ks, int SKp, int nbP, int ldc,
            size_t batchA, size_t batchB, int batchBias)
{
    constexpr int THREADS = 256;
    constexpr int ROWS = TM + 128;
    constexpr int CH = ROWS * 4 / THREADS;
    constexpr int WMC = TM / 64;
    constexpr int ABUF = TM * LDK;
    constexpr int BBUF = 128 * LDK;

    extern __shared__ __align__(16) unsigned short smem[];
    unsigned short* sA = smem;                 // [2][ABUF]
    unsigned short* sB = smem + 2 * ABUF;      // [2][BBUF]

    const int tid = threadIdx.x;
    const int wid = tid >> 5, lane = tid & 31;
    const int z  = blockIdx.z;
    const int wm = (wid % WMC) * 64;
    const int wn = (wid / WMC) * 32;

    const int NIT = Ks / 32;
    const int koff = (MODE == 4) ? z * NIT : 0;

    if (!PERSIST) {
        A  += (size_t)z * batchA;
        Bm += (size_t)z * batchB;
    }
    if (MODE == 2 || MODE == 3) bias += (size_t)z * batchBias;

    const uint32_t sA_base = smem_u32(sA);
    const uint32_t sB_base = smem_u32(sB);
    const int aRow = wm + (lane & 15);
    const int aKof = (lane >> 4) * 8;
    const int bRow = wn + ((lane & 7) | ((lane >> 4) << 3));
    const int bKof = ((lane >> 3) & 1) * 8;

    auto run_tile = [&](int m0, int n0) {
        // staging maps (cp.async)
        const unsigned short* gp[CH];
        uint32_t sdA[CH];
        bool isA_[CH];
        #pragma unroll
        for (int t = 0; t < CH; t++) {
            int id = tid + t * THREADS;
            int r = id >> 2, q = id & 3;
            if (r < TM) {
                gp[t] = A + (size_t)(m0 + r) * SKp + q * 8;
                sdA[t] = smem_u32(sA + r * LDK + q * 8);
                isA_[t] = true;
            } else {
                gp[t] = Bm + (size_t)(n0 + r - TM) * SKp + q * 8;
                sdA[t] = smem_u32(sB + (r - TM) * LDK + q * 8);
                isA_[t] = false;
            }
        }

        float acc[4][4][4];
        #pragma unroll
        for (int i = 0; i < 4; i++)
            #pragma unroll
            for (int j = 0; j < 4; j++)
                #pragma unroll
                for (int q = 0; q < 4; q++) acc[i][j][q] = 0.f;

        auto stage = [&](int k, int buf) {
            int kg = k + koff;
            int kA = kg;
            int kB = (TERMS == 2) ? ((kg < nbP) ? kg : kg - nbP) : kg;
            #pragma unroll
            for (int t = 0; t < CH; t++) {
                const unsigned short* src = gp[t] + (size_t)(isA_[t] ? kA : kB) * 32;
                uint32_t dst = sdA[t] + (uint32_t)buf * (isA_[t] ? ABUF : BBUF) * 2;
                cp_async16(dst, src);
            }
            CP_COMMIT();
        };

        stage(0, 0);
        CP_WAIT0();
        __syncthreads();

        for (int it = 0; it < NIT; it++) {
            const int cur = it & 1;
            const bool more = (it + 1) < NIT;
            if (more) stage(it + 1, cur ^ 1);

            const uint32_t aBuf = sA_base + cur * (ABUF * 2);
            const uint32_t bBuf = sB_base + cur * (BBUF * 2);
            #pragma unroll
            for (int ks = 0; ks < 32; ks += 16) {
                uint32_t af[4][4], bf[4][2];
                #pragma unroll
                for (int mt = 0; mt < 4; mt++)
                    ldmatrix_x4(af[mt][0], af[mt][1], af[mt][2], af[mt][3],
                                aBuf + (uint32_t)(((aRow + mt * 16) * LDK + ks + aKof) * 2));
                #pragma unroll
                for (int np = 0; np < 2; np++)
                    ldmatrix_x4(bf[np * 2][0], bf[np * 2][1], bf[np * 2 + 1][0], bf[np * 2 + 1][1],
                                bBuf + (uint32_t)(((bRow + np * 16) * LDK + ks + bKof) * 2));
                #pragma unroll
                for (int mt = 0; mt < 4; mt++)
                    #pragma unroll
                    for (int nt = 0; nt < 4; nt++)
                        mma_16816(acc[mt][nt], af[mt], bf[nt]);
            }
            if (more) CP_WAIT0();
            __syncthreads();
        }

        // epilogue
        const int erow = lane >> 2;
        const int ecol = (lane & 3) * 2;
        #pragma unroll
        for (int mt = 0; mt < 4; mt++) {
            #pragma unroll
            for (int nt = 0; nt < 4; nt++) {
                const int r0 = m0 + wm + mt * 16 + erow;
                const int c  = n0 + wn + nt * 8 + ecol;
                const float* v = acc[mt][nt];
                if (MODE == 0) {
                    #pragma unroll
                    for (int hr = 0; hr < 2; hr++) {
                        uint32_t pk = (uint32_t)__half_as_ushort(__float2half_rn(v[hr * 2]))
                                    | ((uint32_t)__half_as_ushort(__float2half_rn(v[hr * 2 + 1])) << 16);
                        *(uint32_t*)&outH[(size_t)(r0 + hr * 8) * ldc + c] = pk;
                    }
                } else if (MODE == 2) {
                    float b0 = bias[c], b1 = bias[c + 1];
                    int zz = c >> 9, f = c & 511;
                    #pragma unroll
                    for (int hr = 0; hr < 2; hr++) {
                        float y0 = fmaxf(v[hr * 2] + b0, 0.f);
                        float y1 = fmaxf(v[hr * 2 + 1] + b1, 0.f);
                        uint32_t pk = (uint32_t)__half_as_ushort(__float2half_rn(y0))
                                    | ((uint32_t)__half_as_ushort(__float2half_rn(y1)) << 16);
                        *(uint32_t*)&outH[((size_t)zz * 1024 + (r0 + hr * 8)) * 512 + f] = pk;
                    }
                } else if (MODE == 3) {
                    // G2: scatter fp16 va into X16 at the <=3 shifted positions.
                    float b0 = bias[c], b1 = bias[c + 1];
                    #pragma unroll
                    for (int hr = 0; hr < 2; hr++) {
                        int b = r0 + hr * 8;
                        float s0 = vx[(size_t)b * 512 + c];
                        float s1 = vx[(size_t)b * 512 + c + 1];
                        float y0 = s0 * fmaxf(v[hr * 2] + b0, 0.f);
                        float y1 = s1 * fmaxf(v[hr * 2 + 1] + b1, 0.f);
                        uint32_t pk = (uint32_t)__half_as_ushort(__float2half_rn(y0))
                                    | ((uint32_t)__half_as_ushort(__float2half_rn(y1)) << 16);
                        #pragma unroll
                        for (int dd = -1; dd <= 1; dd++) {
                            int i = z + dd;
                            if (i >= 0 && i <= 7) {
                                int di = 1 - dd;
                                *(uint32_t*)&outH[(size_t)(b * 8 + i) * 1536 + di * 512 + c] = pk;
                            }
                        }
                    }
                } else {  // MODE 4: raw float partial, z-offset
                    float* o = outF + (size_t)z * batchBias;
                    *(float2*)&o[(size_t)r0 * ldc + c] = make_float2(v[0], v[1]);
                    *(float2*)&o[(size_t)(r0 + 8) * ldc + c] = make_float2(v[2], v[3]);
                }
            }
        }
    };

    if (PERSIST) {
        const int ntiles = (int)batchA;
        const int ntx = nbP;
        for (int tile = blockIdx.x; tile < ntiles; tile += gridDim.x)
            run_tile((tile / ntx) * TM, (tile % ntx) * 128);
    } else {
        run_tile(blockIdx.y * TM, blockIdx.x * 128);
    }
}

// ---------------- pool: Y16 -> p16 (vectorized, 2 c per thread) ----------------
__global__ void pool16_kernel(const unsigned short* __restrict__ Y,
                              const float* __restrict__ c1b) {
    int idx = blockIdx.x * blockDim.x + threadIdx.x;   // 1024*256
    int c2 = (idx & 255) * 2, b = idx >> 8;
    float2 bias = *(const float2*)(c1b + c2);
    float m00[2] = {-1e30f, -1e30f}, m01[2] = {-1e30f, -1e30f};
    float m10[2] = {-1e30f, -1e30f}, m11[2] = {-1e30f, -1e30f};
    #pragma unroll
    for (int i = 0; i < 8; i++) {
        size_t base = (size_t)(b * 8 + i) * 1536;
        uint32_t uM = *(const uint32_t*)(Y + base + c2);
        uint32_t uB = *(const uint32_t*)(Y + base + 512 + c2);
        uint32_t uC = *(const uint32_t*)(Y + base + 1024 + c2);
        #pragma unroll
        for (int s = 0; s < 2; s++) {
            float yM = __half2float(__ushort_as_half((unsigned short)(uM >> (16 * s))));
            float yB = __half2float(__ushort_as_half((unsigned short)(uB >> (16 * s))));
            float yC = __half2float(__ushort_as_half((unsigned short)(uC >> (16 * s))));
            float vL = fmaxf(yM - yB, yM);
            float vR = fmaxf(yM - yC, yM);
            if (i < 4) { m00[s] = fmaxf(m00[s], vL); m01[s] = fmaxf(m01[s], vR); }
            else       { m10[s] = fmaxf(m10[s], vL); m11[s] = fmaxf(m11[s], vR); }
        }
    }
    Pack8 o;
    float bb[2] = {bias.x, bias.y};
    #pragma unroll
    for (int s = 0; s < 2; s++) {
        o.s[s * 4 + 0] = __half_as_ushort(__float2half_rn(m00[s] + bb[s]));
        o.s[s * 4 + 1] = __half_as_ushort(__float2half_rn(m01[s] + bb[s]));
        o.s[s * 4 + 2] = __half_as_ushort(__float2half_rn(m10[s] + bb[s]));
        o.s[s * 4 + 3] = __half_as_ushort(__float2half_rn(m11[s] + bb[s]));
    }
    *(uint4*)(g_p16 + (size_t)b * 2048 + c2 * 4) = o.v;
}

// ---------------- G3 reduce: sum 4 partials + bias, relu ----------------
__global__ void reduce_relu_kernel(const float* __restrict__ parts,
                                   const float* __restrict__ bias,
                                   float* __restrict__ out) {
    int idx = blockIdx.x * blockDim.x + threadIdx.x;   // 1024*512/4
    size_t e = (size_t)idx * 4;
    int c = (int)(e & 511);
    float4 a = *(const float4*)(parts + e);
    float4 b = *(const float4*)(parts + e + 524288);
    float4 d = *(const float4*)(parts + e + 2 * 524288);
    float4 f = *(const float4*)(parts + e + 3 * 524288);
    float4 bi = *(const float4*)(bias + c);
    float4 r;
    r.x = fmaxf(a.x + b.x + d.x + f.x + bi.x, 0.f);
    r.y = fmaxf(a.y + b.y + d.y + f.y + bi.y, 0.f);
    r.z = fmaxf(a.z + b.z + d.z + f.z + bi.z, 0.f);
    r.w = fmaxf(a.w + b.w + d.w + f.w + bi.w, 0.f);
    *(float4*)(out + e) = r;
}

// ---------------- launch ----------------
extern "C" void kernel_launch(void* const* d_in, const int* in_sizes, int n_in,
                              void* d_out, int out_size) {
    (void)in_sizes; (void)n_in; (void)out_size;
    const float* vx  = (const float*)d_in[0];
    const float* ax  = (const float*)d_in[1];
    const float* W1  = (const float*)d_in[2];
    const float* b1  = (const float*)d_in[3];
    const float* W2  = (const float*)d_in[4];
    const float* b2  = (const float*)d_in[5];
    const float* c1w = (const float*)d_in[6];
    const float* c1b = (const float*)d_in[7];
    const float* c2w = (const float*)d_in[8];
    const float* c2b = (const float*)d_in[9];
    float* out = (float*)d_out;

    void *p_xcat16, *p_W16, *p_h16, *p_W216, *p_X16, *p_W3, *p_Y16, *p_p16, *p_A216, *p_part;
    cudaGetSymbolAddress(&p_xcat16, g_xcat16);
    cudaGetSymbolAddress(&p_W16,    g_W16);
    cudaGetSymbolAddress(&p_h16,    g_h16);
    cudaGetSymbolAddress(&p_W216,   g_W216);
    cudaGetSymbolAddress(&p_X16,    g_X16);
    cudaGetSymbolAddress(&p_W3,     g_W3);
    cudaGetSymbolAddress(&p_Y16,    g_Y16);
    cudaGetSymbolAddress(&p_p16,    g_p16);
    cudaGetSymbolAddress(&p_A216,   g_A216);
    cudaGetSymbolAddress(&p_part,   g_part);

    const int SM128 = (2 * 128 + 2 * 128) * LDK * 2;  // 40960
    cudaFuncSetAttribute((const void*)hmma_kernel<128, 2, 1, false>, cudaFuncAttributeMaxDynamicSharedMemorySize, SM128);
    cudaFuncSetAttribute((const void*)hmma_kernel<128, 3, 1, false>, cudaFuncAttributeMaxDynamicSharedMemorySize, SM128);
    cudaFuncSetAttribute((const void*)hmma_kernel<128, 0, 1, true>,  cudaFuncAttributeMaxDynamicSharedMemorySize, SM128);
    cudaFuncSetAttribute((const void*)hmma_kernel<128, 4, 1, false>, cudaFuncAttributeMaxDynamicSharedMemorySize, SM128);

    // fused operand builders
    builders_kernel<<<8832, 256>>>(vx, ax, W1, W2, c2w, c1w);

    // GEMM1 (1-term): h16 = fp16(relu(xcat16*W16^T + b1)); K=1024
    hmma_kernel<128, 2, 1, false><<<dim3(32, 8), 256, SM128>>>(
        (const unsigned short*)p_xcat16, (const unsigned short*)p_W16, b1,
        nullptr, (unsigned short*)p_h16, nullptr,
        1024, 1024, 0, 0, 0, 0, 0);

    // GEMM2 (1-term, batch z): scatter X16 = shifted fp16 va; K=512
    hmma_kernel<128, 3, 1, false><<<dim3(4, 8, 8), 256, SM128>>>(
        (const unsigned short*)p_h16, (const unsigned short*)p_W216, b2,
        nullptr, (unsigned short*)p_X16, vx,
        512, 512, 0, 0, (size_t)1024 * 512, (size_t)512 * 512, 512);

    // conv GEMM (1-term, persistent 296 CTAs): Y16 = X16*W3^T; K=1536, 768 tiles
    hmma_kernel<128, 0, 1, true><<<296, 256, SM128>>>(
        (const unsigned short*)p_X16, (const unsigned short*)p_W3, nullptr,
        nullptr, (unsigned short*)p_Y16, nullptr,
        1536, 1536, /*ntx=*/12, 1536, /*ntiles=*/768, 0, 0);

    // pool -> p16 (fp16, vectorized)
    pool16_kernel<<<1024, 256>>>((const unsigned short*)p_Y16, c1b);

    // GEMM3 (1-term, split-K=4): part_z = p16*A216^T over K-slice z; K=2048
    hmma_kernel<128, 4, 1, false><<<dim3(4, 8, 4), 256, SM128>>>(
        (const unsigned short*)p_p16, (const unsigned short*)p_A216, nullptr,
        (float*)p_part, nullptr, nullptr,
        512, 2048, 0, 512, 0, 0, 1024 * 512);

    // reduce partials + bias + relu -> out
    reduce_relu_kernel<<<512, 256>>>((const float*)p_part, c2b, out);
}

// round 16
// speedup vs baseline: 2.9681x; 1.1441x over previous
#include <cuda_runtime.h>
#include <cuda_fp16.h>
#include <cstdint>
#include <cstddef>

// B=1024, F=512, N=8 — HMMA fp16 (fp32 accum), all GEMMs 1-term fp16.
// 3-stage cp.async pipeline (wait_group 1) to hide gmem latency at occ-2.
// G1: h16. G2: scatters di-shifted conv operand X16. conv (persistent): Y16.
// pool (vectorized) -> p16. G3: split-K=4 + reduce. Builders fused.

#define LDK 40   // smem row stride in halves (80B, conflict-free ldmatrix)
#define NSTG 3   // pipeline stages

// ---------------- static scratch ----------------
__device__ unsigned short g_xcat16[(size_t)1024 * 1024];  // fp16 [vx|ax]
__device__ unsigned short g_W16[(size_t)4096 * 1024];     // fp16 W1
__device__ unsigned short g_h16[(size_t)8 * 1024 * 512];  // fp16 h, [z][b][f]
__device__ unsigned short g_W216[(size_t)4096 * 512];     // fp16 W2
__device__ unsigned short g_X16[(size_t)8192 * 1536];     // conv A (scatter-written;
                                                          // boundary blocks stay bss-zero)
__device__ unsigned short g_W3[(size_t)1536 * 1536];      // conv B, fp16
__device__ unsigned short g_Y16[(size_t)8192 * 1536];     // conv out, fp16
__device__ unsigned short g_p16[(size_t)1024 * 2048];     // pooled, fp16
__device__ unsigned short g_A216[(size_t)512 * 2048];     // conv2-collapsed, fp16
__device__ float g_part[(size_t)4 * 1024 * 512];          // G3 split-K partials

// ---------------- helpers ----------------
union Pack8 { unsigned short s[8]; uint4 v; };
__device__ __forceinline__ uint32_t smem_u32(const void* p) {
    uint32_t a;
    asm("{ .reg .u64 t; cvta.to.shared.u64 t, %1; cvt.u32.u64 %0, t; }" : "=r"(a) : "l"(p));
    return a;
}
__device__ __forceinline__ void ldmatrix_x4(uint32_t& r0, uint32_t& r1, uint32_t& r2, uint32_t& r3,
                                            uint32_t addr) {
    asm volatile("ldmatrix.sync.aligned.m8n8.x4.shared.b16 {%0,%1,%2,%3}, [%4];"
                 : "=r"(r0), "=r"(r1), "=r"(r2), "=r"(r3) : "r"(addr));
}
__device__ __forceinline__ void mma_16816(float* c, const uint32_t* a, const uint32_t* b) {
    asm volatile("mma.sync.aligned.m16n8k16.row.col.f32.f16.f16.f32 "
                 "{%0,%1,%2,%3}, {%4,%5,%6,%7}, {%8,%9}, {%0,%1,%2,%3};"
                 : "+f"(c[0]), "+f"(c[1]), "+f"(c[2]), "+f"(c[3])
                 : "r"(a[0]), "r"(a[1]), "r"(a[2]), "r"(a[3]), "r"(b[0]), "r"(b[1]));
}
__device__ __forceinline__ void cp_async16(uint32_t dst, const void* src) {
    asm volatile("cp.async.cg.shared.global [%0], [%1], 16;" :: "r"(dst), "l"(src));
}
#define CP_COMMIT() asm volatile("cp.async.commit_group;" ::: "memory")
#define CP_WAIT0()  asm volatile("cp.async.wait_group 0;" ::: "memory")
#define CP_WAIT1()  asm volatile("cp.async.wait_group 1;" ::: "memory")

// ---------------- fused operand builders ----------------
// blocks [0,512): concat16   [512,2560): W1->fp16   [2560,3584): W2->fp16
// [3584,7680): conv2-collapse A2   [7680,8832): conv1 W3 build
__global__ void builders_kernel(const float* __restrict__ vx, const float* __restrict__ ax,
                                const float* __restrict__ W1, const float* __restrict__ W2,
                                const float* __restrict__ w2c, const float* __restrict__ c1w) {
    const int bid = blockIdx.x;
    const int tid = threadIdx.x;
    if (bid < 512) {
        int idx = bid * 256 + tid;               // 1024*128
        int kv = idx & 127, b = idx >> 7;
        const float* src = (kv < 64) ? (vx + (size_t)b * 512 + kv * 8)
                                     : (ax + (size_t)b * 512 + (kv - 64) * 8);
        float4 x0 = *(const float4*)src, x1 = *(const float4*)(src + 4);
        float vals[8] = {x0.x, x0.y, x0.z, x0.w, x1.x, x1.y, x1.z, x1.w};
        Pack8 h;
        #pragma unroll
        for (int j = 0; j < 8; j++) h.s[j] = __half_as_ushort(__float2half_rn(vals[j]));
        *(uint4*)(g_xcat16 + (size_t)b * 1024 + kv * 8) = h.v;
    } else if (bid < 3584) {
        const float* src; unsigned short* dst; int idx;
        if (bid < 2560) { src = W1; dst = g_W16;  idx = (bid - 512) * 256 + tid; }
        else            { src = W2; dst = g_W216; idx = (bid - 2560) * 256 + tid; }
        const float* s = src + (size_t)idx * 8;
        float4 x0 = *(const float4*)s, x1 = *(const float4*)(s + 4);
        float vals[8] = {x0.x, x0.y, x0.z, x0.w, x1.x, x1.y, x1.z, x1.w};
        Pack8 h;
        #pragma unroll
        for (int j = 0; j < 8; j++) h.s[j] = __half_as_ushort(__float2half_rn(vals[j]));
        *(uint4*)(dst + (size_t)idx * 8) = h.v;
    } else if (bid < 7680) {
        int idx = (bid - 3584) * 256 + tid;      // 512*512*4
        int q = idx & 3;
        int cf = idx >> 2;
        int f = cf & 511;
        int c = cf >> 9;
        int ip = q >> 1, jp = q & 1;
        const float* wb = w2c + (size_t)(c * 512 + f) * 9;
        float s = 0.f;
        #pragma unroll
        for (int i = 0; i < 2; i++)
            #pragma unroll
            for (int j = 0; j < 2; j++)
                s += wb[(ip - i + 1) * 3 + (jp - j + 1)];
        g_A216[(size_t)c * 2048 + f * 4 + q] = __half_as_ushort(__float2half_rn(0.25f * s));
    } else {
        int idx = (bid - 7680) * 256 + tid;      // 1536*3*64
        int fg = idx & 63;
        int di = (idx >> 6) % 3;
        int n  = idx / 192;
        int t = n >> 9, c = n & 511;
        Pack8 hi;
        #pragma unroll
        for (int j = 0; j < 8; j++) {
            int f = fg * 8 + j;
            size_t base = ((size_t)(c * 512 + f) * 3 + di) * 3;
            float w;
            if (t == 0)      w = c1w[base] + c1w[base + 1] + c1w[base + 2];
            else if (t == 1) w = c1w[base];
            else             w = c1w[base + 2];
            hi.s[j] = __half_as_ushort(__float2half_rn(w));
        }
        *(uint4*)(g_W3 + (size_t)n * 1536 + di * 512 + fg * 8) = hi.v;
    }
}

// ---------------- unified HMMA GEMM (3-stage cp.async pipeline) ----------------
// MODE 0: fp16 store (conv Y)       MODE 2: fp16 h store [z][b][f] (G1)
// MODE 3: X16 scatter epilogue (G2) MODE 4: raw float partial store, z-offset (G3)
// PERSIST: 1D grid of resident CTAs loops tiles; ntiles=batchA, ntx=nbP.
template <int TM, int MODE, int TERMS, bool PERSIST>
__global__ void __launch_bounds__(256, 2)
hmma_kernel(const unsigned short* __restrict__ A, const unsigned short* __restrict__ Bm,
            const float* __restrict__ bias, float* __restrict__ outF,
            unsigned short* __restrict__ outH, const float* __restrict__ vx,
            int Ks, int SKp, int nbP, int ldc,
            size_t batchA, size_t batchB, int batchBias)
{
    constexpr int THREADS = 256;
    constexpr int ROWS = TM + 128;
    constexpr int CH = ROWS * 4 / THREADS;
    constexpr int WMC = TM / 64;
    constexpr int ABUF = TM * LDK;
    constexpr int BBUF = 128 * LDK;

    extern __shared__ __align__(16) unsigned short smem[];
    unsigned short* sA = smem;                      // [NSTG][ABUF]
    unsigned short* sB = smem + NSTG * ABUF;        // [NSTG][BBUF]

    const int tid = threadIdx.x;
    const int wid = tid >> 5, lane = tid & 31;
    const int z  = blockIdx.z;
    const int wm = (wid % WMC) * 64;
    const int wn = (wid / WMC) * 32;

    const int NIT = Ks / 32;
    const int koff = (MODE == 4) ? z * NIT : 0;

    if (!PERSIST) {
        A  += (size_t)z * batchA;
        Bm += (size_t)z * batchB;
    }
    if (MODE == 2 || MODE == 3) bias += (size_t)z * batchBias;

    const uint32_t sA_base = smem_u32(sA);
    const uint32_t sB_base = smem_u32(sB);
    const int aRow = wm + (lane & 15);
    const int aKof = (lane >> 4) * 8;
    const int bRow = wn + ((lane & 7) | ((lane >> 4) << 3));
    const int bKof = ((lane >> 3) & 1) * 8;

    auto run_tile = [&](int m0, int n0) {
        // staging maps (cp.async)
        const unsigned short* gp[CH];
        uint32_t sdA[CH];
        bool isA_[CH];
        #pragma unroll
        for (int t = 0; t < CH; t++) {
            int id = tid + t * THREADS;
            int r = id >> 2, q = id & 3;
            if (r < TM) {
                gp[t] = A + (size_t)(m0 + r) * SKp + q * 8;
                sdA[t] = smem_u32(sA + r * LDK + q * 8);
                isA_[t] = true;
            } else {
                gp[t] = Bm + (size_t)(n0 + r - TM) * SKp + q * 8;
                sdA[t] = smem_u32(sB + (r - TM) * LDK + q * 8);
                isA_[t] = false;
            }
        }

        float acc[4][4][4];
        #pragma unroll
        for (int i = 0; i < 4; i++)
            #pragma unroll
            for (int j = 0; j < 4; j++)
                #pragma unroll
                for (int q = 0; q < 4; q++) acc[i][j][q] = 0.f;

        auto stage = [&](int k, int buf) {
            int kg = k + koff;
            int kA = kg;
            int kB = (TERMS == 2) ? ((kg < nbP) ? kg : kg - nbP) : kg;
            #pragma unroll
            for (int t = 0; t < CH; t++) {
                const unsigned short* src = gp[t] + (size_t)(isA_[t] ? kA : kB) * 32;
                uint32_t dst = sdA[t] + (uint32_t)buf * (isA_[t] ? ABUF : BBUF) * 2;
                cp_async16(dst, src);
            }
            CP_COMMIT();
        };

        // prime 2 stages
        stage(0, 0);
        if (NIT > 1) stage(1, 1);

        int cur = 0, nxt2 = 2;
        for (int it = 0; it < NIT; it++) {
            if (it == NIT - 1) { CP_WAIT0(); } else { CP_WAIT1(); }
            __syncthreads();

            const uint32_t aBuf = sA_base + (uint32_t)cur * ABUF * 2;
            const uint32_t bBuf = sB_base + (uint32_t)cur * BBUF * 2;
            #pragma unroll
            for (int ks = 0; ks < 32; ks += 16) {
                uint32_t af[4][4], bf[4][2];
                #pragma unroll
                for (int mt = 0; mt < 4; mt++)
                    ldmatrix_x4(af[mt][0], af[mt][1], af[mt][2], af[mt][3],
                                aBuf + (uint32_t)(((aRow + mt * 16) * LDK + ks + aKof) * 2));
                #pragma unroll
                for (int np = 0; np < 2; np++)
                    ldmatrix_x4(bf[np * 2][0], bf[np * 2][1], bf[np * 2 + 1][0], bf[np * 2 + 1][1],
                                bBuf + (uint32_t)(((bRow + np * 16) * LDK + ks + bKof) * 2));
                #pragma unroll
                for (int mt = 0; mt < 4; mt++)
                    #pragma unroll
                    for (int nt = 0; nt < 4; nt++)
                        mma_16816(acc[mt][nt], af[mt], bf[nt]);
            }
            if (it + 2 < NIT) stage(it + 2, nxt2);
            cur = (cur == NSTG - 1) ? 0 : cur + 1;
            nxt2 = (nxt2 == NSTG - 1) ? 0 : nxt2 + 1;
        }
        __syncthreads();   // protect smem reuse by next persistent tile

        // epilogue
        const int erow = lane >> 2;
        const int ecol = (lane & 3) * 2;
        #pragma unroll
        for (int mt = 0; mt < 4; mt++) {
            #pragma unroll
            for (int nt = 0; nt < 4; nt++) {
                const int r0 = m0 + wm + mt * 16 + erow;
                const int c  = n0 + wn + nt * 8 + ecol;
                const float* v = acc[mt][nt];
                if (MODE == 0) {
                    #pragma unroll
                    for (int hr = 0; hr < 2; hr++) {
                        uint32_t pk = (uint32_t)__half_as_ushort(__float2half_rn(v[hr * 2]))
                                    | ((uint32_t)__half_as_ushort(__float2half_rn(v[hr * 2 + 1])) << 16);
                        *(uint32_t*)&outH[(size_t)(r0 + hr * 8) * ldc + c] = pk;
                    }
                } else if (MODE == 2) {
                    float b0 = bias[c], b1 = bias[c + 1];
                    int zz = c >> 9, f = c & 511;
                    #pragma unroll
                    for (int hr = 0; hr < 2; hr++) {
                        float y0 = fmaxf(v[hr * 2] + b0, 0.f);
                        float y1 = fmaxf(v[hr * 2 + 1] + b1, 0.f);
                        uint32_t pk = (uint32_t)__half_as_ushort(__float2half_rn(y0))
                                    | ((uint32_t)__half_as_ushort(__float2half_rn(y1)) << 16);
                        *(uint32_t*)&outH[((size_t)zz * 1024 + (r0 + hr * 8)) * 512 + f] = pk;
                    }
                } else if (MODE == 3) {
                    // G2: scatter fp16 va into X16 at the <=3 shifted positions.
                    float b0 = bias[c], b1 = bias[c + 1];
                    #pragma unroll
                    for (int hr = 0; hr < 2; hr++) {
                        int b = r0 + hr * 8;
                        float s0 = vx[(size_t)b * 512 + c];
                        float s1 = vx[(size_t)b * 512 + c + 1];
                        float y0 = s0 * fmaxf(v[hr * 2] + b0, 0.f);
                        float y1 = s1 * fmaxf(v[hr * 2 + 1] + b1, 0.f);
                        uint32_t pk = (uint32_t)__half_as_ushort(__float2half_rn(y0))
                                    | ((uint32_t)__half_as_ushort(__float2half_rn(y1)) << 16);
                        #pragma unroll
                        for (int dd = -1; dd <= 1; dd++) {
                            int i = z + dd;
                            if (i >= 0 && i <= 7) {
                                int di = 1 - dd;
                                *(uint32_t*)&outH[(size_t)(b * 8 + i) * 1536 + di * 512 + c] = pk;
                            }
                        }
                    }
                } else {  // MODE 4: raw float partial, z-offset
                    float* o = outF + (size_t)z * batchBias;
                    *(float2*)&o[(size_t)r0 * ldc + c] = make_float2(v[0], v[1]);
                    *(float2*)&o[(size_t)(r0 + 8) * ldc + c] = make_float2(v[2], v[3]);
                }
            }
        }
    };

    if (PERSIST) {
        const int ntiles = (int)batchA;
        const int ntx = nbP;
        for (int tile = blockIdx.x; tile < ntiles; tile += gridDim.x)
            run_tile((tile / ntx) * TM, (tile % ntx) * 128);
    } else {
        run_tile(blockIdx.y * TM, blockIdx.x * 128);
    }
}

// ---------------- pool: Y16 -> p16 (vectorized, 2 c per thread) ----------------
__global__ void pool16_kernel(const unsigned short* __restrict__ Y,
                              const float* __restrict__ c1b) {
    int idx = blockIdx.x * blockDim.x + threadIdx.x;   // 1024*256
    int c2 = (idx & 255) * 2, b = idx >> 8;
    float2 bias = *(const float2*)(c1b + c2);
    float m00[2] = {-1e30f, -1e30f}, m01[2] = {-1e30f, -1e30f};
    float m10[2] = {-1e30f, -1e30f}, m11[2] = {-1e30f, -1e30f};
    #pragma unroll
    for (int i = 0; i < 8; i++) {
        size_t base = (size_t)(b * 8 + i) * 1536;
        uint32_t uM = *(const uint32_t*)(Y + base + c2);
        uint32_t uB = *(const uint32_t*)(Y + base + 512 + c2);
        uint32_t uC = *(const uint32_t*)(Y + base + 1024 + c2);
        #pragma unroll
        for (int s = 0; s < 2; s++) {
            float yM = __half2float(__ushort_as_half((unsigned short)(uM >> (16 * s))));
            float yB = __half2float(__ushort_as_half((unsigned short)(uB >> (16 * s))));
            float yC = __half2float(__ushort_as_half((unsigned short)(uC >> (16 * s))));
            float vL = fmaxf(yM - yB, yM);
            float vR = fmaxf(yM - yC, yM);
            if (i < 4) { m00[s] = fmaxf(m00[s], vL); m01[s] = fmaxf(m01[s], vR); }
            else       { m10[s] = fmaxf(m10[s], vL); m11[s] = fmaxf(m11[s], vR); }
        }
    }
    Pack8 o;
    float bb[2] = {bias.x, bias.y};
    #pragma unroll
    for (int s = 0; s < 2; s++) {
        o.s[s * 4 + 0] = __half_as_ushort(__float2half_rn(m00[s] + bb[s]));
        o.s[s * 4 + 1] = __half_as_ushort(__float2half_rn(m01[s] + bb[s]));
        o.s[s * 4 + 2] = __half_as_ushort(__float2half_rn(m10[s] + bb[s]));
        o.s[s * 4 + 3] = __half_as_ushort(__float2half_rn(m11[s] + bb[s]));
    }
    *(uint4*)(g_p16 + (size_t)b * 2048 + c2 * 4) = o.v;
}

// ---------------- G3 reduce: sum 4 partials + bias, relu ----------------
__global__ void reduce_relu_kernel(const float* __restrict__ parts,
                                   const float* __restrict__ bias,
                                   float* __restrict__ out) {
    int idx = blockIdx.x * blockDim.x + threadIdx.x;   // 1024*512/4
    size_t e = (size_t)idx * 4;
    int c = (int)(e & 511);
    float4 a = *(const float4*)(parts + e);
    float4 b = *(const float4*)(parts + e + 524288);
    float4 d = *(const float4*)(parts + e + 2 * 524288);
    float4 f = *(const float4*)(parts + e + 3 * 524288);
    float4 bi = *(const float4*)(bias + c);
    float4 r;
    r.x = fmaxf(a.x + b.x + d.x + f.x + bi.x, 0.f);
    r.y = fmaxf(a.y + b.y + d.y + f.y + bi.y, 0.f);
    r.z = fmaxf(a.z + b.z + d.z + f.z + bi.z, 0.f);
    r.w = fmaxf(a.w + b.w + d.w + f.w + bi.w, 0.f);
    *(float4*)(out + e) = r;
}

// ---------------- launch ----------------
extern "C" void kernel_launch(void* const* d_in, const int* in_sizes, int n_in,
                              void* d_out, int out_size) {
    (void)in_sizes; (void)n_in; (void)out_size;
    const float* vx  = (const float*)d_in[0];
    const float* ax  = (const float*)d_in[1];
    const float* W1  = (const float*)d_in[2];
    const float* b1  = (const float*)d_in[3];
    const float* W2  = (const float*)d_in[4];
    const float* b2  = (const float*)d_in[5];
    const float* c1w = (const float*)d_in[6];
    const float* c1b = (const float*)d_in[7];
    const float* c2w = (const float*)d_in[8];
    const float* c2b = (const float*)d_in[9];
    float* out = (float*)d_out;

    void *p_xcat16, *p_W16, *p_h16, *p_W216, *p_X16, *p_W3, *p_Y16, *p_p16, *p_A216, *p_part;
    cudaGetSymbolAddress(&p_xcat16, g_xcat16);
    cudaGetSymbolAddress(&p_W16,    g_W16);
    cudaGetSymbolAddress(&p_h16,    g_h16);
    cudaGetSymbolAddress(&p_W216,   g_W216);
    cudaGetSymbolAddress(&p_X16,    g_X16);
    cudaGetSymbolAddress(&p_W3,     g_W3);
    cudaGetSymbolAddress(&p_Y16,    g_Y16);
    cudaGetSymbolAddress(&p_p16,    g_p16);
    cudaGetSymbolAddress(&p_A216,   g_A216);
    cudaGetSymbolAddress(&p_part,   g_part);

    const int SM3 = NSTG * (128 + 128) * LDK * 2;  // 61440
    cudaFuncSetAttribute((const void*)hmma_kernel<128, 2, 1, false>, cudaFuncAttributeMaxDynamicSharedMemorySize, SM3);
    cudaFuncSetAttribute((const void*)hmma_kernel<128, 3, 1, false>, cudaFuncAttributeMaxDynamicSharedMemorySize, SM3);
    cudaFuncSetAttribute((const void*)hmma_kernel<128, 0, 1, true>,  cudaFuncAttributeMaxDynamicSharedMemorySize, SM3);
    cudaFuncSetAttribute((const void*)hmma_kernel<128, 4, 1, false>, cudaFuncAttributeMaxDynamicSharedMemorySize, SM3);

    // fused operand builders
    builders_kernel<<<8832, 256>>>(vx, ax, W1, W2, c2w, c1w);

    // GEMM1 (1-term): h16 = fp16(relu(xcat16*W16^T + b1)); K=1024
    hmma_kernel<128, 2, 1, false><<<dim3(32, 8), 256, SM3>>>(
        (const unsigned short*)p_xcat16, (const unsigned short*)p_W16, b1,
        nullptr, (unsigned short*)p_h16, nullptr,
        1024, 1024, 0, 0, 0, 0, 0);

    // GEMM2 (1-term, batch z): scatter X16 = shifted fp16 va; K=512
    hmma_kernel<128, 3, 1, false><<<dim3(4, 8, 8), 256, SM3>>>(
        (const unsigned short*)p_h16, (const unsigned short*)p_W216, b2,
        nullptr, (unsigned short*)p_X16, vx,
        512, 512, 0, 0, (size_t)1024 * 512, (size_t)512 * 512, 512);

    // conv GEMM (1-term, persistent 296 CTAs): Y16 = X16*W3^T; K=1536, 768 tiles
    hmma_kernel<128, 0, 1, true><<<296, 256, SM3>>>(
        (const unsigned short*)p_X16, (const unsigned short*)p_W3, nullptr,
        nullptr, (unsigned short*)p_Y16, nullptr,
        1536, 1536, /*ntx=*/12, 1536, /*ntiles=*/768, 0, 0);

    // pool -> p16 (fp16, vectorized)
    pool16_kernel<<<1024, 256>>>((const unsigned short*)p_Y16, c1b);

    // GEMM3 (1-term, split-K=4): part_z = p16*A216^T over K-slice z; K=2048
    hmma_kernel<128, 4, 1, false><<<dim3(4, 8, 4), 256, SM3>>>(
        (const unsigned short*)p_p16, (const unsigned short*)p_A216, nullptr,
        (float*)p_part, nullptr, nullptr,
        512, 2048, 0, 512, 0, 0, 1024 * 512);

    // reduce partials + bias + relu -> out
    reduce_relu_kernel<<<512, 256>>>((const float*)p_part, c2b, out);
}